// round 6
// baseline (speedup 1.0000x reference)
#include <cuda_runtime.h>
#include <math.h>
#include <stdint.h>

// Problem constants
#define Bn 2
#define Cn 256
#define Hn 96
#define Wn 96
#define HW (Hn*Wn)
#define CGn 64
#define KKn 9
#define KTOT 2304
#define NCHUNK 72           // K chunks of 32
#define NTILE 144           // 64-px tiles per image

// Output layout
#define OUT_LOGITS 0
#define OUT_BBOX   18432
#define OUT_SHAPE  92160
#define OUT_LOC    129024

// GEMM smem strides (floats)
#define LDA 40
#define LDB 40
#define LDD 136

// Dynamic smem byte offsets (double buffered)
#define SM_A0   0            // 64*40*4  = 10240
#define SM_A1   10240
#define SM_B0   20480        // 256*40*4 = 40960
#define SM_B1   61440
#define SM_RED  102400       // 5*256*4  = 5120
#define SM_SHV  107520       // 512
#define SM_TOTAL 108544

// Scratch (device globals)
__device__ float g_x   [Bn*HW*Cn];     // feature NHWC, tf32, k-interleaved/32
__device__ float g_t   [Bn*HW*Cn];     // conv1 output NHWC (fp32, natural order)
__device__ float g_off [Bn*HW*72];
__device__ float g_w1tc[KTOT*Cn];      // [chunk][oc][32 slots], tf32, interleaved
__device__ float g_w2tc[KTOT*Cn];

// k-interleave: slot s holds original k = invk(s); frag pair (t, t+4) -> slots (2t, 2t+1)
__host__ __device__ __forceinline__ int invk32(int s) {
    return (s & 24) | ((s >> 1) & 3) | ((s & 1) << 2);
}

// ---------------- helpers ---------------------------------------------------
__device__ __forceinline__ uint32_t smem_u32(const void* p) {
    uint32_t a;
    asm("{ .reg .u64 t; cvta.to.shared.u64 t, %1; cvt.u32.u64 %0, t; }"
        : "=r"(a) : "l"(p));
    return a;
}
__device__ __forceinline__ float tf32r(float x) {
    uint32_t u;
    asm("cvt.rna.tf32.f32 %0, %1;" : "=r"(u) : "f"(x));
    return __uint_as_float(u);
}
__device__ __forceinline__ void mma8(float* d, const uint32_t* a,
                                     uint32_t b0, uint32_t b1) {
    asm volatile(
        "mma.sync.aligned.m16n8k8.row.col.f32.tf32.tf32.f32 "
        "{%0,%1,%2,%3},{%4,%5,%6,%7},{%8,%9},{%0,%1,%2,%3};"
        : "+f"(d[0]), "+f"(d[1]), "+f"(d[2]), "+f"(d[3])
        : "r"(a[0]), "r"(a[1]), "r"(a[2]), "r"(a[3]), "r"(b0), "r"(b1));
}
#define CPA16(dst, src) \
    asm volatile("cp.async.ca.shared.global [%0], [%1], 16;" \
                 :: "r"(dst), "l"(src))
#define CPA16Z(dst, src, n) \
    asm volatile("cp.async.ca.shared.global [%0], [%1], 16, %2;" \
                 :: "r"(dst), "l"(src), "r"(n))
#define CPA_COMMIT() asm volatile("cp.async.commit_group;")
#define CPA_WAIT0()  asm volatile("cp.async.wait_group 0;")

// ---------------------------------------------------------------------------
// Kernel 1: NCHW -> NHWC transpose, tf32-rounded, channel-interleaved per 32
// ---------------------------------------------------------------------------
__global__ void k_transpose_feat(const float* __restrict__ x) {
    __shared__ float tile[32][33];
    int b  = blockIdx.z;
    int p0 = blockIdx.x * 32;
    int c0 = blockIdx.y * 32;
    int txi = threadIdx.x, tyi = threadIdx.y;  // 32 x 8
    #pragma unroll
    for (int s = 0; s < 32; s += 8)
        tile[tyi + s][txi] = x[(size_t)(b*Cn + c0 + tyi + s)*HW + p0 + txi];
    __syncthreads();
    const int csel = invk32(txi);
    #pragma unroll
    for (int s = 0; s < 32; s += 8)
        g_x[(size_t)(b*HW + p0 + tyi + s)*Cn + c0 + txi] = tf32r(tile[csel][tyi + s]);
}

// ---------------------------------------------------------------------------
// Kernel 2: weight re-layout into chunked [chunk][oc][32] tf32, k-interleaved
// ---------------------------------------------------------------------------
__global__ void k_prep_w(const float* __restrict__ conv_w,
                         const float* __restrict__ adapt_w) {
    const int n = KTOT*Cn;
    int idx = blockIdx.x * blockDim.x + threadIdx.x;
    if (idx < n) {
        int dk = invk32(idx & 31);
        int o  = (idx >> 5) & 255;
        int ch = idx >> 13;
        int tap = ch >> 3;
        int c   = (ch & 7)*32 + dk;
        g_w1tc[idx] = tf32r(conv_w[(o*Cn + c)*KKn + tap]);
    } else if (idx < 2*n) {
        int j  = idx - n;
        int dk = invk32(j & 31);
        int o  = (j >> 5) & 255;
        int ch = j >> 13;
        int gt = ch >> 1;
        int ci = (ch & 1)*32 + dk;
        int g  = gt / 9, tap = gt % 9;
        g_w2tc[j] = tf32r(adapt_w[(o*Cn + g*CGn + ci)*KKn + tap]);
    }
}

// ---------------------------------------------------------------------------
// GEMM core macro: LDS.64 fragment loads, 4 ksteps, 2x8 atoms per warp
// ---------------------------------------------------------------------------
#define MMA_CHUNK(Abuf, Bbuf)                                                  \
    _Pragma("unroll")                                                          \
    for (int ks = 0; ks < 4; ++ks) {                                           \
        const int k0 = ks*8;                                                   \
        uint32_t a[2][4];                                                      \
        _Pragma("unroll")                                                      \
        for (int ma = 0; ma < 2; ++ma) {                                       \
            const float2 lo = *(const float2*)&(Abuf)[(wm*32+ma*16+g)*LDA + k0 + 2*t];   \
            const float2 hi = *(const float2*)&(Abuf)[(wm*32+ma*16+g+8)*LDA + k0 + 2*t]; \
            a[ma][0] = __float_as_uint(lo.x); a[ma][2] = __float_as_uint(lo.y);\
            a[ma][1] = __float_as_uint(hi.x); a[ma][3] = __float_as_uint(hi.y);\
        }                                                                      \
        _Pragma("unroll")                                                      \
        for (int na = 0; na < 8; ++na) {                                       \
            const float2 bb = *(const float2*)&(Bbuf)[(wn*64+na*8+g)*LDB + k0 + 2*t];    \
            mma8(d[0][na], a[0], __float_as_uint(bb.x), __float_as_uint(bb.y));\
            mma8(d[1][na], a[1], __float_as_uint(bb.x), __float_as_uint(bb.y));\
        }                                                                      \
    }

// ---------------------------------------------------------------------------
// Kernel 3: conv3x3 via mma.sync tf32, double-buffered, fused heads
// ---------------------------------------------------------------------------
__global__ void __launch_bounds__(256, 2)
k_conv1_mma(const float* __restrict__ conv_b_,
            const float* __restrict__ loc_w,  const float* __restrict__ loc_b,
            const float* __restrict__ shape_w,const float* __restrict__ shape_b,
            const float* __restrict__ offset_w,
            float* __restrict__ out) {
    extern __shared__ __align__(128) char smem[];
    float* AsmB[2] = {(float*)(smem + SM_A0), (float*)(smem + SM_A1)};
    float* BsmB[2] = {(float*)(smem + SM_B0), (float*)(smem + SM_B1)};
    float* Dsm = (float*)(smem + SM_B0);     // reuse after GEMM
    float* red = (float*)(smem + SM_RED);
    float* shv = (float*)(smem + SM_SHV);
    const uint32_t sA0 = smem_u32(AsmB[0]), sA1 = smem_u32(AsmB[1]);
    const uint32_t sB0 = smem_u32(BsmB[0]), sB1 = smem_u32(BsmB[1]);

    const int tid = threadIdx.x, wid = tid >> 5, lane = tid & 31;
    const int g = lane >> 2, t = lane & 3;
    const int wm = wid & 1, wn = wid >> 1;

    const int tt = blockIdx.x;
    const int b  = blockIdx.y;
    const int y0 = (tt / 6) * 4, x0 = (tt % 6) * 16;

    const int pS = tid >> 2, qS = tid & 3;
    const int ySr = pS >> 4, xSc = pS & 15;

    float d[2][8][4];
    #pragma unroll
    for (int i = 0; i < 2; ++i)
        #pragma unroll
        for (int j = 0; j < 8; ++j)
            #pragma unroll
            for (int k = 0; k < 4; ++k) d[i][j][k] = 0.f;

    const uint32_t daOff = (uint32_t)(pS*LDA + qS*8)*4;
    const uint32_t dbOff = (uint32_t)(tid*LDB)*4;

    auto stage = [&](int c, int nb) {
        const uint32_t da = (nb ? sA1 : sA0) + daOff;
        const uint32_t db = (nb ? sB1 : sB0) + dbOff;
        const int tap = c >> 3, cin0 = (c & 7) << 5;
        const int dy = tap/3 - 1, dx = tap%3 - 1;
        const int yy = y0 + ySr + dy, xx = x0 + xSc + dx;
        const bool ok = (yy >= 0 && yy < Hn && xx >= 0 && xx < Wn);
        const float* src = ok
            ? &g_x[((size_t)((b*Hn + yy)*Wn + xx))*Cn + cin0 + qS*8] : g_x;
        const uint32_t nbytes = ok ? 16u : 0u;
        CPA16Z(da,      src,     nbytes);
        CPA16Z(da + 16, src + 4, nbytes);
        const float* ws = &g_w1tc[(size_t)c*8192 + tid*32];
        #pragma unroll
        for (int q = 0; q < 8; ++q) CPA16(db + q*16, ws + q*4);
        CPA_COMMIT();
    };

    stage(0, 0);
    CPA_WAIT0();
    __syncthreads();

    for (int c = 0; c < NCHUNK; ++c) {
        const int buf = c & 1;
        if (c < NCHUNK-1) stage(c+1, buf ^ 1);
        MMA_CHUNK(AsmB[buf], BsmB[buf]);
        if (c < NCHUNK-1) CPA_WAIT0();
        __syncthreads();
    }

    // ---- epilogue: bias + relu in place, head partials -----------------
    float P0[4], P1[4], P2[4];
    #pragma unroll
    for (int s = 0; s < 4; ++s) { P0[s] = 0.f; P1[s] = 0.f; P2[s] = 0.f; }

    #pragma unroll
    for (int ma = 0; ma < 2; ++ma)
        #pragma unroll
        for (int na = 0; na < 8; ++na)
            #pragma unroll
            for (int ci = 0; ci < 4; ++ci) {
                const int oc = wn*64 + na*8 + 2*t + (ci & 1);
                const int slot = ma*2 + (ci >> 1);
                float v = fmaxf(d[ma][na][ci] + conv_b_[oc], 0.f);
                d[ma][na][ci] = v;
                P0[slot] += v * loc_w[oc];
                P1[slot] += v * shape_w[oc];
                P2[slot] += v * shape_w[Cn + oc];
            }
    #pragma unroll
    for (int s = 0; s < 4; ++s) {
        P0[s] += __shfl_xor_sync(0xffffffffu, P0[s], 1);
        P0[s] += __shfl_xor_sync(0xffffffffu, P0[s], 2);
        P1[s] += __shfl_xor_sync(0xffffffffu, P1[s], 1);
        P1[s] += __shfl_xor_sync(0xffffffffu, P1[s], 2);
        P2[s] += __shfl_xor_sync(0xffffffffu, P2[s], 2);
        P2[s] += __shfl_xor_sync(0xffffffffu, P2[s], 1);
    }
    if (t == 0) {
        #pragma unroll
        for (int s = 0; s < 4; ++s) {
            const int row = wm*32 + (s >> 1)*16 + g + (s & 1)*8;
            red[0*256 + row*4 + wn] = P0[s];
            red[1*256 + row*4 + wn] = P1[s];
            red[2*256 + row*4 + wn] = P2[s];
        }
    }
    __syncthreads();

    if (tid < 64) {
        const int px = tid;
        float sl = 0.f, s0 = 0.f, s1 = 0.f;
        #pragma unroll
        for (int w = 0; w < 4; ++w) {
            sl += red[0*256 + px*4 + w];
            s0 += red[1*256 + px*4 + w];
            s1 += red[2*256 + px*4 + w];
        }
        const int y = y0 + (px >> 4), xg = x0 + (px & 15);
        const int pix = y*Wn + xg;
        out[OUT_LOC + b*HW + pix] = sl + loc_b[0];
        const float a0 = s0 + shape_b[0];
        const float a1 = s1 + shape_b[1];
        out[OUT_SHAPE + (b*2 + 0)*HW + pix] = a0;
        out[OUT_SHAPE + (b*2 + 1)*HW + pix] = a1;
        shv[px*2 + 0] = a0;
        shv[px*2 + 1] = a1;
    }
    __syncthreads();

    // offsets: 64 px x 72 ch
    for (int idx = tid; idx < 64*72; idx += 256) {
        const int p = idx / 72, j = idx % 72;
        const int y = y0 + (p >> 4), xg = x0 + (p & 15);
        float v = shv[p*2]*offset_w[j*2] + shv[p*2+1]*offset_w[j*2+1];
        g_off[((size_t)((b*Hn + y)*Wn + xg))*72 + j] = v;
    }

    // g_t staging (natural channel order) for coalesced stores
    const int pixS = (b*Hn + y0 + ySr)*Wn + x0 + xSc;
    #pragma unroll
    for (int h = 0; h < 2; ++h) {
        __syncthreads();
        if ((wn >> 1) == h) {
            #pragma unroll
            for (int ma = 0; ma < 2; ++ma)
                #pragma unroll
                for (int na = 0; na < 8; ++na)
                    #pragma unroll
                    for (int ci = 0; ci < 4; ++ci) {
                        const int row = wm*32 + ma*16 + g + (ci >> 1)*8;
                        const int col = (wn & 1)*64 + na*8 + 2*t + (ci & 1);
                        Dsm[row*LDD + col] = d[ma][na][ci];
                    }
        }
        __syncthreads();
        #pragma unroll
        for (int j = 0; j < 8; ++j) {
            float4 v = *(const float4*)&Dsm[pS*LDD + qS*32 + j*4];
            *(float4*)&g_t[(size_t)pixS*Cn + h*128 + qS*32 + j*4] = v;
        }
    }
}

// ---------------------------------------------------------------------------
// Kernel 4: deformable conv via mma.sync tf32, double-buffered gather pipeline
// ---------------------------------------------------------------------------
__global__ void __launch_bounds__(256, 2)
k_deform_mma(const float* __restrict__ cls_w, const float* __restrict__ cls_b,
             const float* __restrict__ bbox_w, const float* __restrict__ bbox_b,
             float* __restrict__ out) {
    extern __shared__ __align__(128) char smem[];
    float* AsmB[2] = {(float*)(smem + SM_A0), (float*)(smem + SM_A1)};
    float* BsmB[2] = {(float*)(smem + SM_B0), (float*)(smem + SM_B1)};
    float* red = (float*)(smem + SM_RED);
    const uint32_t sB0 = smem_u32(BsmB[0]), sB1 = smem_u32(BsmB[1]);

    const int tid = threadIdx.x, wid = tid >> 5, lane = tid & 31;
    const int g = lane >> 2, t = lane & 3;
    const int wm = wid & 1, wn = wid >> 1;

    const int tt = blockIdx.x;
    const int b  = blockIdx.y;
    const int y0 = (tt / 6) * 4, x0 = (tt % 6) * 16;

    const int pS = tid >> 2, qS = tid & 3;
    const int yP = y0 + (pS >> 4), xP = x0 + (pS & 15);
    const int pixb = (b*Hn + yP)*Wn + xP;

    float d[2][8][4];
    #pragma unroll
    for (int i = 0; i < 2; ++i)
        #pragma unroll
        for (int j = 0; j < 8; ++j)
            #pragma unroll
            for (int k = 0; k < 4; ++k) d[i][j][k] = 0.f;

    const uint32_t dbOff = (uint32_t)(tid*LDB)*4;
    int   ga[4];
    float gw[4];
    float4 u[4][2];   // gathered corners, 8 ch each

    auto calc_meta = [&](int gt) {
        const int gg = gt / 9, tap = gt - gg*9;
        const int dy = tap/3 - 1, dx = tap%3 - 1;
        const float offy = g_off[(size_t)pixb*72 + gt*2 + 0];
        const float offx = g_off[(size_t)pixb*72 + gt*2 + 1];
        const float pyf = (float)(yP + dy) + offy;
        const float pxf = (float)(xP + dx) + offx;
        const float y0f = floorf(pyf), x0f = floorf(pxf);
        const float wy = pyf - y0f, wx = pxf - x0f;
        const int yi = (int)y0f, xi = (int)x0f;
        #pragma unroll
        for (int cy = 0; cy < 2; ++cy)
            #pragma unroll
            for (int cx = 0; cx < 2; ++cx) {
                const int k = cy*2 + cx;
                const int yc = yi + cy, xc = xi + cx;
                const bool valid = (yc >= 0 && yc < Hn && xc >= 0 && xc < Wn);
                const int ycc = min(max(yc, 0), Hn - 1);
                const int xcc = min(max(xc, 0), Wn - 1);
                const float wv = (cy ? wy : 1.f - wy) * (cx ? wx : 1.f - wx);
                gw[k] = valid ? wv : 0.f;
                ga[k] = ((b*Hn + ycc)*Wn + xcc)*Cn + gg*CGn;
            }
    };

    auto issue_loads = [&](int n, int nb) {
        const uint32_t db = (nb ? sB1 : sB0) + dbOff;
        const float* ws = &g_w2tc[(size_t)n*8192 + tid*32];
        #pragma unroll
        for (int q = 0; q < 8; ++q) CPA16(db + q*16, ws + q*4);
        CPA_COMMIT();
        if ((n & 1) == 0) calc_meta(n >> 1);
        const int chb = (n & 1)*32 + qS*8;
        #pragma unroll
        for (int k = 0; k < 4; ++k) {
            u[k][0] = *(const float4*)&g_t[(size_t)ga[k] + chb];
            u[k][1] = *(const float4*)&g_t[(size_t)ga[k] + chb + 4];
        }
    };

    auto combine_store = [&](int nb) {
        float r[8];
        #pragma unroll
        for (int h = 0; h < 2; ++h) {
            r[h*4+0] = tf32r(gw[0]*u[0][h].x + gw[1]*u[1][h].x + gw[2]*u[2][h].x + gw[3]*u[3][h].x);
            r[h*4+1] = tf32r(gw[0]*u[0][h].y + gw[1]*u[1][h].y + gw[2]*u[2][h].y + gw[3]*u[3][h].y);
            r[h*4+2] = tf32r(gw[0]*u[0][h].z + gw[1]*u[1][h].z + gw[2]*u[2][h].z + gw[3]*u[3][h].z);
            r[h*4+3] = tf32r(gw[0]*u[0][h].w + gw[1]*u[1][h].w + gw[2]*u[2][h].w + gw[3]*u[3][h].w);
        }
        // k-interleaved STS: slot order j = 0,4,1,5 | 2,6,3,7
        float* dst = &AsmB[nb][pS*LDA + qS*8];
        *(float4*)dst       = make_float4(r[0], r[4], r[1], r[5]);
        *(float4*)(dst + 4) = make_float4(r[2], r[6], r[3], r[7]);
    };

    issue_loads(0, 0);
    combine_store(0);
    CPA_WAIT0();
    __syncthreads();

    for (int c = 0; c < NCHUNK; ++c) {
        const int buf = c & 1;
        if (c < NCHUNK-1) issue_loads(c+1, buf ^ 1);
        MMA_CHUNK(AsmB[buf], BsmB[buf]);
        if (c < NCHUNK-1) { combine_store(buf ^ 1); CPA_WAIT0(); }
        __syncthreads();
    }

    // ---- epilogue: relu + cls/bbox head partials -----------------------
    float P[5][4];
    #pragma unroll
    for (int h = 0; h < 5; ++h)
        #pragma unroll
        for (int s = 0; s < 4; ++s) P[h][s] = 0.f;

    #pragma unroll
    for (int ma = 0; ma < 2; ++ma)
        #pragma unroll
        for (int na = 0; na < 8; ++na)
            #pragma unroll
            for (int ci = 0; ci < 4; ++ci) {
                const int oc = wn*64 + na*8 + 2*t + (ci & 1);
                const int slot = ma*2 + (ci >> 1);
                const float v = fmaxf(d[ma][na][ci], 0.f);
                P[0][slot] += v * cls_w[oc];
                P[1][slot] += v * bbox_w[oc];
                P[2][slot] += v * bbox_w[Cn + oc];
                P[3][slot] += v * bbox_w[2*Cn + oc];
                P[4][slot] += v * bbox_w[3*Cn + oc];
            }
    #pragma unroll
    for (int h = 0; h < 5; ++h)
        #pragma unroll
        for (int s = 0; s < 4; ++s) {
            P[h][s] += __shfl_xor_sync(0xffffffffu, P[h][s], 1);
            P[h][s] += __shfl_xor_sync(0xffffffffu, P[h][s], 2);
        }
    if (t == 0) {
        #pragma unroll
        for (int s = 0; s < 4; ++s) {
            const int row = wm*32 + (s >> 1)*16 + g + (s & 1)*8;
            #pragma unroll
            for (int h = 0; h < 5; ++h)
                red[h*256 + row*4 + wn] = P[h][s];
        }
    }
    __syncthreads();

    if (tid < 64) {
        const int px = tid;
        float s[5] = {0.f, 0.f, 0.f, 0.f, 0.f};
        #pragma unroll
        for (int h = 0; h < 5; ++h)
            #pragma unroll
            for (int w = 0; w < 4; ++w)
                s[h] += red[h*256 + px*4 + w];
        const int y = y0 + (px >> 4), xg = x0 + (px & 15);
        const int pix = y*Wn + xg;
        out[OUT_LOGITS + b*HW + pix]        = s[0] + cls_b[0];
        out[OUT_BBOX + (b*4 + 0)*HW + pix]  = s[1] + bbox_b[0];
        out[OUT_BBOX + (b*4 + 1)*HW + pix]  = s[2] + bbox_b[1];
        out[OUT_BBOX + (b*4 + 2)*HW + pix]  = s[3] + bbox_b[2];
        out[OUT_BBOX + (b*4 + 3)*HW + pix]  = s[4] + bbox_b[3];
    }
}

// ---------------------------------------------------------------------------
extern "C" void kernel_launch(void* const* d_in, const int* in_sizes, int n_in,
                              void* d_out, int out_size) {
    const float* feature  = (const float*)d_in[0];
    const float* conv_w   = (const float*)d_in[1];
    const float* conv_b   = (const float*)d_in[2];
    const float* loc_w    = (const float*)d_in[3];
    const float* loc_b    = (const float*)d_in[4];
    const float* shape_w  = (const float*)d_in[5];
    const float* shape_b  = (const float*)d_in[6];
    const float* offset_w = (const float*)d_in[7];
    const float* adapt_w  = (const float*)d_in[8];
    const float* cls_w    = (const float*)d_in[9];
    const float* cls_b    = (const float*)d_in[10];
    const float* bbox_w   = (const float*)d_in[11];
    const float* bbox_b   = (const float*)d_in[12];
    float* out = (float*)d_out;

    cudaFuncSetAttribute(k_conv1_mma,
        cudaFuncAttributeMaxDynamicSharedMemorySize, SM_TOTAL);
    cudaFuncSetAttribute(k_deform_mma,
        cudaFuncAttributeMaxDynamicSharedMemorySize, SM_TOTAL);

    k_transpose_feat<<<dim3(HW/32, Cn/32, Bn), dim3(32, 8)>>>(feature);
    k_prep_w<<<(2*KTOT*Cn + 255)/256, 256>>>(conv_w, adapt_w);
    k_conv1_mma<<<dim3(NTILE, Bn), 256, SM_TOTAL>>>(conv_b, loc_w, loc_b,
                                                    shape_w, shape_b,
                                                    offset_w, out);
    k_deform_mma<<<dim3(NTILE, Bn), 256, SM_TOTAL>>>(cls_w, cls_b,
                                                     bbox_w, bbox_b, out);
}

// round 7
// speedup vs baseline: 1.1308x; 1.1308x over previous
#include <cuda_runtime.h>
#include <math.h>
#include <stdint.h>

// Problem constants
#define Bn 2
#define Cn 256
#define Hn 96
#define Wn 96
#define HW (Hn*Wn)
#define CGn 64
#define KKn 9
#define KTOT 2304
#define NCHUNK 72           // K chunks of 32
#define NTILE 144           // 64-px tiles per image

// Output layout
#define OUT_LOGITS 0
#define OUT_BBOX   18432
#define OUT_SHAPE  92160
#define OUT_LOC    129024

// GEMM smem strides (floats) — LDA/LDB=36: scalar frag loads conflict-free
#define LDA 36
#define LDB 36
#define LDD 136

// Dynamic smem byte offsets (double buffered)
#define SM_A0   0            // 64*36*4  = 9216
#define SM_A1   9216
#define SM_B0   18432        // 256*36*4 = 36864
#define SM_B1   55296
#define SM_RED  92160        // 5*256*4  = 5120
#define SM_SHV  97280        // 512
#define SM_TOTAL 97792

// Scratch (device globals)
__device__ float g_x   [Bn*HW*Cn];     // feature NHWC (tf32-rounded)
__device__ float g_t   [Bn*HW*Cn];     // conv1 output NHWC (fp32)
__device__ float g_off [Bn*HW*72];
__device__ float g_w1tc[KTOT*Cn];      // [chunk][oc][32], tf32
__device__ float g_w2tc[KTOT*Cn];

// ---------------- helpers ---------------------------------------------------
__device__ __forceinline__ uint32_t smem_u32(const void* p) {
    uint32_t a;
    asm("{ .reg .u64 t; cvta.to.shared.u64 t, %1; cvt.u32.u64 %0, t; }"
        : "=r"(a) : "l"(p));
    return a;
}
__device__ __forceinline__ float tf32r(float x) {
    uint32_t u;
    asm("cvt.rna.tf32.f32 %0, %1;" : "=r"(u) : "f"(x));
    return __uint_as_float(u);
}
__device__ __forceinline__ void mma8(float* d, const uint32_t* a,
                                     uint32_t b0, uint32_t b1) {
    asm volatile(
        "mma.sync.aligned.m16n8k8.row.col.f32.tf32.tf32.f32 "
        "{%0,%1,%2,%3},{%4,%5,%6,%7},{%8,%9},{%0,%1,%2,%3};"
        : "+f"(d[0]), "+f"(d[1]), "+f"(d[2]), "+f"(d[3])
        : "r"(a[0]), "r"(a[1]), "r"(a[2]), "r"(a[3]), "r"(b0), "r"(b1));
}
#define CPA16(dst, src) \
    asm volatile("cp.async.ca.shared.global [%0], [%1], 16;" \
                 :: "r"(dst), "l"(src))
#define CPA16Z(dst, src, n) \
    asm volatile("cp.async.ca.shared.global [%0], [%1], 16, %2;" \
                 :: "r"(dst), "l"(src), "r"(n))
#define CPA_COMMIT() asm volatile("cp.async.commit_group;")
#define CPA_WAIT0()  asm volatile("cp.async.wait_group 0;")

// ---------------------------------------------------------------------------
// Kernel 1: NCHW -> NHWC transpose of feature, tf32-rounded
// ---------------------------------------------------------------------------
__global__ void k_transpose_feat(const float* __restrict__ x) {
    __shared__ float tile[32][33];
    int b  = blockIdx.z;
    int p0 = blockIdx.x * 32;
    int c0 = blockIdx.y * 32;
    int txi = threadIdx.x, tyi = threadIdx.y;  // 32 x 8
    #pragma unroll
    for (int s = 0; s < 32; s += 8)
        tile[tyi + s][txi] = x[(size_t)(b*Cn + c0 + tyi + s)*HW + p0 + txi];
    __syncthreads();
    #pragma unroll
    for (int s = 0; s < 32; s += 8)
        g_x[(size_t)(b*HW + p0 + tyi + s)*Cn + c0 + txi] = tf32r(tile[txi][tyi + s]);
}

// ---------------------------------------------------------------------------
// Kernel 2: weight re-layout into chunked [chunk][oc][32] tf32 tiles
// ---------------------------------------------------------------------------
__global__ void k_prep_w(const float* __restrict__ conv_w,
                         const float* __restrict__ adapt_w) {
    const int n = KTOT*Cn;
    int idx = blockIdx.x * blockDim.x + threadIdx.x;
    if (idx < n) {
        int dk = idx & 31;
        int o  = (idx >> 5) & 255;
        int ch = idx >> 13;
        int tap = ch >> 3;
        int c   = (ch & 7)*32 + dk;
        g_w1tc[idx] = tf32r(conv_w[(o*Cn + c)*KKn + tap]);
    } else if (idx < 2*n) {
        int j  = idx - n;
        int dk = j & 31;
        int o  = (j >> 5) & 255;
        int ch = j >> 13;
        int gt = ch >> 1;
        int ci = (ch & 1)*32 + dk;
        int g  = gt / 9, tap = gt % 9;
        g_w2tc[j] = tf32r(adapt_w[(o*Cn + g*CGn + ci)*KKn + tap]);
    }
}

// GEMM core: scalar LDS frag loads (conflict-free with LD*=36), 4 ksteps
#define MMA_CHUNK(Abuf, Bbuf)                                                  \
    _Pragma("unroll")                                                          \
    for (int ks = 0; ks < 4; ++ks) {                                           \
        const int k0 = ks*8;                                                   \
        uint32_t a[2][4];                                                      \
        _Pragma("unroll")                                                      \
        for (int ma = 0; ma < 2; ++ma) {                                       \
            const float* ap = &(Abuf)[(wm*32 + ma*16 + g)*LDA + k0 + t];       \
            a[ma][0] = __float_as_uint(ap[0]);                                 \
            a[ma][1] = __float_as_uint(ap[8*LDA]);                             \
            a[ma][2] = __float_as_uint(ap[4]);                                 \
            a[ma][3] = __float_as_uint(ap[8*LDA + 4]);                         \
        }                                                                      \
        _Pragma("unroll")                                                      \
        for (int na = 0; na < 8; ++na) {                                       \
            const float* bp = &(Bbuf)[(wn*64 + na*8 + g)*LDB + k0 + t];        \
            const uint32_t b0 = __float_as_uint(bp[0]);                        \
            const uint32_t b1 = __float_as_uint(bp[4]);                        \
            mma8(d[0][na], a[0], b0, b1);                                      \
            mma8(d[1][na], a[1], b0, b1);                                      \
        }                                                                      \
    }

// ---------------------------------------------------------------------------
// Kernel 3: conv3x3 via mma.sync tf32, double-buffered, fused heads
// ---------------------------------------------------------------------------
__global__ void __launch_bounds__(256, 2)
k_conv1_mma(const float* __restrict__ conv_b_,
            const float* __restrict__ loc_w,  const float* __restrict__ loc_b,
            const float* __restrict__ shape_w,const float* __restrict__ shape_b,
            const float* __restrict__ offset_w,
            float* __restrict__ out) {
    extern __shared__ __align__(128) char smem[];
    float* Asm0 = (float*)(smem + SM_A0);
    float* Asm1 = (float*)(smem + SM_A1);
    float* Bsm0 = (float*)(smem + SM_B0);
    float* Bsm1 = (float*)(smem + SM_B1);
    float* Dsm  = (float*)(smem + SM_B0);    // reuse after GEMM
    float* red  = (float*)(smem + SM_RED);
    float* shv  = (float*)(smem + SM_SHV);

    const int tid = threadIdx.x, wid = tid >> 5, lane = tid & 31;
    const int g = lane >> 2, t = lane & 3;
    const int wm = wid & 1, wn = wid >> 1;

    const int tt = blockIdx.x;
    const int b  = blockIdx.y;
    const int y0 = (tt / 6) * 4, x0 = (tt % 6) * 16;

    const int pS = tid >> 2, qS = tid & 3;
    const int ySr = pS >> 4, xSc = pS & 15;

    float d[2][8][4];
    #pragma unroll
    for (int i = 0; i < 2; ++i)
        #pragma unroll
        for (int j = 0; j < 8; ++j)
            #pragma unroll
            for (int k = 0; k < 4; ++k) d[i][j][k] = 0.f;

    const uint32_t daOff = (uint32_t)(pS*LDA + qS*8)*4;
    const uint32_t dbOff = (uint32_t)(tid*LDB)*4;
    const uint32_t da0 = smem_u32(Asm0) + daOff, da1 = smem_u32(Asm1) + daOff;
    const uint32_t db0 = smem_u32(Bsm0) + dbOff, db1 = smem_u32(Bsm1) + dbOff;

    auto stage = [&](int c, uint32_t da, uint32_t db) {
        const int tap = c >> 3, cin0 = (c & 7) << 5;
        const int dy = tap/3 - 1, dx = tap%3 - 1;
        const int yy = y0 + ySr + dy, xx = x0 + xSc + dx;
        const bool ok = (yy >= 0 && yy < Hn && xx >= 0 && xx < Wn);
        const float* src = ok
            ? &g_x[((size_t)((b*Hn + yy)*Wn + xx))*Cn + cin0 + qS*8] : g_x;
        const uint32_t nbytes = ok ? 16u : 0u;
        CPA16Z(da,      src,     nbytes);
        CPA16Z(da + 16, src + 4, nbytes);
        const float* ws = &g_w1tc[(size_t)c*8192 + tid*32];
        #pragma unroll
        for (int q = 0; q < 8; ++q) CPA16(db + q*16, ws + q*4);
        CPA_COMMIT();
    };

    stage(0, da0, db0);
    CPA_WAIT0();
    __syncthreads();

    #pragma unroll 1
    for (int c = 0; c < NCHUNK; c += 2) {
        if (c + 1 < NCHUNK) stage(c + 1, da1, db1);
        MMA_CHUNK(Asm0, Bsm0);
        CPA_WAIT0();
        __syncthreads();
        if (c + 2 < NCHUNK) stage(c + 2, da0, db0);
        MMA_CHUNK(Asm1, Bsm1);
        CPA_WAIT0();
        __syncthreads();
    }

    // ---- epilogue: bias + relu in place, head partials -----------------
    float P0[4], P1[4], P2[4];
    #pragma unroll
    for (int s = 0; s < 4; ++s) { P0[s] = 0.f; P1[s] = 0.f; P2[s] = 0.f; }

    #pragma unroll
    for (int ma = 0; ma < 2; ++ma)
        #pragma unroll
        for (int na = 0; na < 8; ++na)
            #pragma unroll
            for (int ci = 0; ci < 4; ++ci) {
                const int oc = wn*64 + na*8 + 2*t + (ci & 1);
                const int slot = ma*2 + (ci >> 1);
                float v = fmaxf(d[ma][na][ci] + conv_b_[oc], 0.f);
                d[ma][na][ci] = v;
                P0[slot] += v * loc_w[oc];
                P1[slot] += v * shape_w[oc];
                P2[slot] += v * shape_w[Cn + oc];
            }
    #pragma unroll
    for (int s = 0; s < 4; ++s) {
        P0[s] += __shfl_xor_sync(0xffffffffu, P0[s], 1);
        P0[s] += __shfl_xor_sync(0xffffffffu, P0[s], 2);
        P1[s] += __shfl_xor_sync(0xffffffffu, P1[s], 1);
        P1[s] += __shfl_xor_sync(0xffffffffu, P1[s], 2);
        P2[s] += __shfl_xor_sync(0xffffffffu, P2[s], 2);
        P2[s] += __shfl_xor_sync(0xffffffffu, P2[s], 1);
    }
    if (t == 0) {
        #pragma unroll
        for (int s = 0; s < 4; ++s) {
            const int row = wm*32 + (s >> 1)*16 + g + (s & 1)*8;
            red[0*256 + row*4 + wn] = P0[s];
            red[1*256 + row*4 + wn] = P1[s];
            red[2*256 + row*4 + wn] = P2[s];
        }
    }
    __syncthreads();

    if (tid < 64) {
        const int px = tid;
        float sl = 0.f, s0 = 0.f, s1 = 0.f;
        #pragma unroll
        for (int w = 0; w < 4; ++w) {
            sl += red[0*256 + px*4 + w];
            s0 += red[1*256 + px*4 + w];
            s1 += red[2*256 + px*4 + w];
        }
        const int y = y0 + (px >> 4), xg = x0 + (px & 15);
        const int pix = y*Wn + xg;
        out[OUT_LOC + b*HW + pix] = sl + loc_b[0];
        const float a0 = s0 + shape_b[0];
        const float a1 = s1 + shape_b[1];
        out[OUT_SHAPE + (b*2 + 0)*HW + pix] = a0;
        out[OUT_SHAPE + (b*2 + 1)*HW + pix] = a1;
        shv[px*2 + 0] = a0;
        shv[px*2 + 1] = a1;
    }
    __syncthreads();

    // offsets: 64 px x 72 ch
    for (int idx = tid; idx < 64*72; idx += 256) {
        const int p = idx / 72, j = idx % 72;
        const int y = y0 + (p >> 4), xg = x0 + (p & 15);
        float v = shv[p*2]*offset_w[j*2] + shv[p*2+1]*offset_w[j*2+1];
        g_off[((size_t)((b*Hn + y)*Wn + xg))*72 + j] = v;
    }

    // g_t staging through smem (2 oc halves) for coalesced stores
    const int pixS = (b*Hn + y0 + ySr)*Wn + x0 + xSc;
    #pragma unroll
    for (int h = 0; h < 2; ++h) {
        __syncthreads();
        if ((wn >> 1) == h) {
            #pragma unroll
            for (int ma = 0; ma < 2; ++ma)
                #pragma unroll
                for (int na = 0; na < 8; ++na)
                    #pragma unroll
                    for (int ci = 0; ci < 4; ++ci) {
                        const int row = wm*32 + ma*16 + g + (ci >> 1)*8;
                        const int col = (wn & 1)*64 + na*8 + 2*t + (ci & 1);
                        Dsm[row*LDD + col] = d[ma][na][ci];
                    }
        }
        __syncthreads();
        #pragma unroll
        for (int j = 0; j < 8; ++j) {
            float4 v = *(const float4*)&Dsm[pS*LDD + qS*32 + j*4];
            *(float4*)&g_t[(size_t)pixS*Cn + h*128 + qS*32 + j*4] = v;
        }
    }
}

// ---------------------------------------------------------------------------
// Kernel 4: deformable conv via mma.sync tf32, double-buffered gather pipeline
// ---------------------------------------------------------------------------
__global__ void __launch_bounds__(256, 2)
k_deform_mma(const float* __restrict__ cls_w, const float* __restrict__ cls_b,
             const float* __restrict__ bbox_w, const float* __restrict__ bbox_b,
             float* __restrict__ out) {
    extern __shared__ __align__(128) char smem[];
    float* Asm0 = (float*)(smem + SM_A0);
    float* Asm1 = (float*)(smem + SM_A1);
    float* Bsm0 = (float*)(smem + SM_B0);
    float* Bsm1 = (float*)(smem + SM_B1);
    float* red  = (float*)(smem + SM_RED);

    const int tid = threadIdx.x, wid = tid >> 5, lane = tid & 31;
    const int g = lane >> 2, t = lane & 3;
    const int wm = wid & 1, wn = wid >> 1;

    const int tt = blockIdx.x;
    const int b  = blockIdx.y;
    const int y0 = (tt / 6) * 4, x0 = (tt % 6) * 16;

    const int pS = tid >> 2, qS = tid & 3;
    const int yP = y0 + (pS >> 4), xP = x0 + (pS & 15);
    const int pixb = (b*Hn + yP)*Wn + xP;

    float d[2][8][4];
    #pragma unroll
    for (int i = 0; i < 2; ++i)
        #pragma unroll
        for (int j = 0; j < 8; ++j)
            #pragma unroll
            for (int k = 0; k < 4; ++k) d[i][j][k] = 0.f;

    const uint32_t dbOff = (uint32_t)(tid*LDB)*4;
    const uint32_t db0 = smem_u32(Bsm0) + dbOff, db1 = smem_u32(Bsm1) + dbOff;

    int    ga[4];
    float  gw[4];
    float4 u[4][2];
    float2 offreg;

    auto calc_meta = [&](float offy, float offx, int gt) {
        const int gg = gt / 9, tap = gt - gg*9;
        const int dy = tap/3 - 1, dx = tap%3 - 1;
        const float pyf = (float)(yP + dy) + offy;
        const float pxf = (float)(xP + dx) + offx;
        const float y0f = floorf(pyf), x0f = floorf(pxf);
        const float wy = pyf - y0f, wx = pxf - x0f;
        const int yi = (int)y0f, xi = (int)x0f;
        #pragma unroll
        for (int cy = 0; cy < 2; ++cy)
            #pragma unroll
            for (int cx = 0; cx < 2; ++cx) {
                const int k = cy*2 + cx;
                const int yc = yi + cy, xc = xi + cx;
                const bool valid = (yc >= 0 && yc < Hn && xc >= 0 && xc < Wn);
                const int ycc = min(max(yc, 0), Hn - 1);
                const int xcc = min(max(xc, 0), Wn - 1);
                const float wv = (cy ? wy : 1.f - wy) * (cx ? wx : 1.f - wx);
                gw[k] = valid ? wv : 0.f;
                ga[k] = ((b*Hn + ycc)*Wn + xcc)*Cn + gg*CGn;
            }
    };

    auto issue_w = [&](int n, uint32_t db) {
        const float* ws = &g_w2tc[(size_t)n*8192 + tid*32];
        #pragma unroll
        for (int q = 0; q < 8; ++q) CPA16(db + q*16, ws + q*4);
        CPA_COMMIT();
    };

    auto issue_u = [&](int n) {
        const int chb = (n & 1)*32 + qS*8;
        #pragma unroll
        for (int k = 0; k < 4; ++k) {
            u[k][0] = *(const float4*)&g_t[(size_t)ga[k] + chb];
            u[k][1] = *(const float4*)&g_t[(size_t)ga[k] + chb + 4];
        }
    };

    auto combine_store = [&](float* Abuf) {
        float* dst = &Abuf[pS*LDA + qS*8];
        float4 r0, r1;
        r0.x = tf32r(gw[0]*u[0][0].x + gw[1]*u[1][0].x + gw[2]*u[2][0].x + gw[3]*u[3][0].x);
        r0.y = tf32r(gw[0]*u[0][0].y + gw[1]*u[1][0].y + gw[2]*u[2][0].y + gw[3]*u[3][0].y);
        r0.z = tf32r(gw[0]*u[0][0].z + gw[1]*u[1][0].z + gw[2]*u[2][0].z + gw[3]*u[3][0].z);
        r0.w = tf32r(gw[0]*u[0][0].w + gw[1]*u[1][0].w + gw[2]*u[2][0].w + gw[3]*u[3][0].w);
        r1.x = tf32r(gw[0]*u[0][1].x + gw[1]*u[1][1].x + gw[2]*u[2][1].x + gw[3]*u[3][1].x);
        r1.y = tf32r(gw[0]*u[0][1].y + gw[1]*u[1][1].y + gw[2]*u[2][1].y + gw[3]*u[3][1].y);
        r1.z = tf32r(gw[0]*u[0][1].z + gw[1]*u[1][1].z + gw[2]*u[2][1].z + gw[3]*u[3][1].z);
        r1.w = tf32r(gw[0]*u[0][1].w + gw[1]*u[1][1].w + gw[2]*u[2][1].w + gw[3]*u[3][1].w);
        *(float4*)dst       = r0;
        *(float4*)(dst + 4) = r1;
    };

    // prologue: meta for gt=0, stage chunk 0 into buf0, prefetch off for gt=1
    offreg = *(const float2*)&g_off[(size_t)pixb*72];
    calc_meta(offreg.x, offreg.y, 0);
    offreg = *(const float2*)&g_off[(size_t)pixb*72 + 2];
    issue_w(0, db0);
    issue_u(0);
    combine_store(Asm0);
    CPA_WAIT0();
    __syncthreads();

    #pragma unroll 1
    for (int c = 0; c < NCHUNK; c += 2) {
        // odd chunk (same gt, sub-chunk 1) -> buf1
        if (c + 1 < NCHUNK) { issue_w(c + 1, db1); issue_u(c + 1); }
        MMA_CHUNK(Asm0, Bsm0);
        if (c + 1 < NCHUNK) combine_store(Asm1);
        CPA_WAIT0();
        __syncthreads();
        // next even chunk (new gt) -> buf0
        if (c + 2 < NCHUNK) {
            const int gt = (c + 2) >> 1;
            calc_meta(offreg.x, offreg.y, gt);
            if (gt + 1 < 36)
                offreg = *(const float2*)&g_off[(size_t)pixb*72 + (gt + 1)*2];
            issue_w(c + 2, db0);
            issue_u(c + 2);
        }
        MMA_CHUNK(Asm1, Bsm1);
        if (c + 2 < NCHUNK) combine_store(Asm0);
        CPA_WAIT0();
        __syncthreads();
    }

    // ---- epilogue: relu + cls/bbox head partials -----------------------
    float P[5][4];
    #pragma unroll
    for (int h = 0; h < 5; ++h)
        #pragma unroll
        for (int s = 0; s < 4; ++s) P[h][s] = 0.f;

    #pragma unroll
    for (int ma = 0; ma < 2; ++ma)
        #pragma unroll
        for (int na = 0; na < 8; ++na)
            #pragma unroll
            for (int ci = 0; ci < 4; ++ci) {
                const int oc = wn*64 + na*8 + 2*t + (ci & 1);
                const int slot = ma*2 + (ci >> 1);
                const float v = fmaxf(d[ma][na][ci], 0.f);
                P[0][slot] += v * cls_w[oc];
                P[1][slot] += v * bbox_w[oc];
                P[2][slot] += v * bbox_w[Cn + oc];
                P[3][slot] += v * bbox_w[2*Cn + oc];
                P[4][slot] += v * bbox_w[3*Cn + oc];
            }
    #pragma unroll
    for (int h = 0; h < 5; ++h)
        #pragma unroll
        for (int s = 0; s < 4; ++s) {
            P[h][s] += __shfl_xor_sync(0xffffffffu, P[h][s], 1);
            P[h][s] += __shfl_xor_sync(0xffffffffu, P[h][s], 2);
        }
    if (t == 0) {
        #pragma unroll
        for (int s = 0; s < 4; ++s) {
            const int row = wm*32 + (s >> 1)*16 + g + (s & 1)*8;
            #pragma unroll
            for (int h = 0; h < 5; ++h)
                red[h*256 + row*4 + wn] = P[h][s];
        }
    }
    __syncthreads();

    if (tid < 64) {
        const int px = tid;
        float s[5] = {0.f, 0.f, 0.f, 0.f, 0.f};
        #pragma unroll
        for (int h = 0; h < 5; ++h)
            #pragma unroll
            for (int w = 0; w < 4; ++w)
                s[h] += red[h*256 + px*4 + w];
        const int y = y0 + (px >> 4), xg = x0 + (px & 15);
        const int pix = y*Wn + xg;
        out[OUT_LOGITS + b*HW + pix]        = s[0] + cls_b[0];
        out[OUT_BBOX + (b*4 + 0)*HW + pix]  = s[1] + bbox_b[0];
        out[OUT_BBOX + (b*4 + 1)*HW + pix]  = s[2] + bbox_b[1];
        out[OUT_BBOX + (b*4 + 2)*HW + pix]  = s[3] + bbox_b[2];
        out[OUT_BBOX + (b*4 + 3)*HW + pix]  = s[4] + bbox_b[3];
    }
}

// ---------------------------------------------------------------------------
extern "C" void kernel_launch(void* const* d_in, const int* in_sizes, int n_in,
                              void* d_out, int out_size) {
    const float* feature  = (const float*)d_in[0];
    const float* conv_w   = (const float*)d_in[1];
    const float* conv_b   = (const float*)d_in[2];
    const float* loc_w    = (const float*)d_in[3];
    const float* loc_b    = (const float*)d_in[4];
    const float* shape_w  = (const float*)d_in[5];
    const float* shape_b  = (const float*)d_in[6];
    const float* offset_w = (const float*)d_in[7];
    const float* adapt_w  = (const float*)d_in[8];
    const float* cls_w    = (const float*)d_in[9];
    const float* cls_b    = (const float*)d_in[10];
    const float* bbox_w   = (const float*)d_in[11];
    const float* bbox_b   = (const float*)d_in[12];
    float* out = (float*)d_out;

    cudaFuncSetAttribute(k_conv1_mma,
        cudaFuncAttributeMaxDynamicSharedMemorySize, SM_TOTAL);
    cudaFuncSetAttribute(k_deform_mma,
        cudaFuncAttributeMaxDynamicSharedMemorySize, SM_TOTAL);

    k_transpose_feat<<<dim3(HW/32, Cn/32, Bn), dim3(32, 8)>>>(feature);
    k_prep_w<<<(2*KTOT*Cn + 255)/256, 256>>>(conv_w, adapt_w);
    k_conv1_mma<<<dim3(NTILE, Bn), 256, SM_TOTAL>>>(conv_b, loc_w, loc_b,
                                                    shape_w, shape_b,
                                                    offset_w, out);
    k_deform_mma<<<dim3(NTILE, Bn), 256, SM_TOTAL>>>(cls_w, cls_b,
                                                     bbox_w, bbox_b, out);
}

// round 8
// speedup vs baseline: 1.5627x; 1.3819x over previous
#include <cuda_runtime.h>
#include <math.h>
#include <stdint.h>

// Problem constants
#define Bn 2
#define Cn 256
#define Hn 96
#define Wn 96
#define HW (Hn*Wn)
#define CGn 64
#define KKn 9
#define KTOT 2304
#define NCHUNK 72           // K chunks of 32

// Output layout
#define OUT_LOGITS 0
#define OUT_BBOX   18432
#define OUT_SHAPE  92160
#define OUT_LOC    129024

// GEMM smem strides (floats) — 36: conflict-free scalar frag loads
#define LDA 36
#define LDB 36

// Dynamic smem byte offsets
#define SM_A    0            // 128*36*4 = 18432
#define SM_B    18432        // 256*36*4 = 36864
#define SM_RED  55296        // 5*512*4  = 10240
#define SM_SHV  65536        // 128*2*4  = 1024
#define SM_TOTAL 66560

// Scratch (device globals)
__device__ float g_x   [Bn*HW*Cn];     // feature NHWC (tf32-rounded)
__device__ float g_t   [Bn*HW*Cn];     // conv1 output NHWC (fp32)
__device__ float g_off [Bn*HW*72];
__device__ float g_w1tc[KTOT*Cn];      // [chunk][oc][32], tf32
__device__ float g_w2tc[KTOT*Cn];

// ---------------- helpers ---------------------------------------------------
__device__ __forceinline__ uint32_t smem_u32(const void* p) {
    uint32_t a;
    asm("{ .reg .u64 t; cvta.to.shared.u64 t, %1; cvt.u32.u64 %0, t; }"
        : "=r"(a) : "l"(p));
    return a;
}
__device__ __forceinline__ float tf32r(float x) {
    uint32_t u;
    asm("cvt.rna.tf32.f32 %0, %1;" : "=r"(u) : "f"(x));
    return __uint_as_float(u);
}
__device__ __forceinline__ void mma8(float* d, const uint32_t* a,
                                     uint32_t b0, uint32_t b1) {
    asm volatile(
        "mma.sync.aligned.m16n8k8.row.col.f32.tf32.tf32.f32 "
        "{%0,%1,%2,%3},{%4,%5,%6,%7},{%8,%9},{%0,%1,%2,%3};"
        : "+f"(d[0]), "+f"(d[1]), "+f"(d[2]), "+f"(d[3])
        : "r"(a[0]), "r"(a[1]), "r"(a[2]), "r"(a[3]), "r"(b0), "r"(b1));
}
#define CPA16(dst, src) \
    asm volatile("cp.async.ca.shared.global [%0], [%1], 16;" \
                 :: "r"(dst), "l"(src))
#define CPA16Z(dst, src, n) \
    asm volatile("cp.async.ca.shared.global [%0], [%1], 16, %2;" \
                 :: "r"(dst), "l"(src), "r"(n))
#define CPA_COMMIT() asm volatile("cp.async.commit_group;")
#define CPA_WAIT0()  asm volatile("cp.async.wait_group 0;")

// ---------------------------------------------------------------------------
// Kernel 1: NCHW -> NHWC transpose of feature, tf32-rounded
// ---------------------------------------------------------------------------
__global__ void k_transpose_feat(const float* __restrict__ x) {
    __shared__ float tile[32][33];
    int b  = blockIdx.z;
    int p0 = blockIdx.x * 32;
    int c0 = blockIdx.y * 32;
    int txi = threadIdx.x, tyi = threadIdx.y;  // 32 x 8
    #pragma unroll
    for (int s = 0; s < 32; s += 8)
        tile[tyi + s][txi] = x[(size_t)(b*Cn + c0 + tyi + s)*HW + p0 + txi];
    __syncthreads();
    #pragma unroll
    for (int s = 0; s < 32; s += 8)
        g_x[(size_t)(b*HW + p0 + tyi + s)*Cn + c0 + txi] = tf32r(tile[txi][tyi + s]);
}

// ---------------------------------------------------------------------------
// Kernel 2: weight re-layout into chunked [chunk][oc][32] tf32 tiles
// ---------------------------------------------------------------------------
__global__ void k_prep_w(const float* __restrict__ conv_w,
                         const float* __restrict__ adapt_w) {
    const int n = KTOT*Cn;
    int idx = blockIdx.x * blockDim.x + threadIdx.x;
    if (idx < n) {
        int dk = idx & 31;
        int o  = (idx >> 5) & 255;
        int ch = idx >> 13;
        int tap = ch >> 3;
        int c   = (ch & 7)*32 + dk;
        g_w1tc[idx] = tf32r(conv_w[(o*Cn + c)*KKn + tap]);
    } else if (idx < 2*n) {
        int j  = idx - n;
        int dk = j & 31;
        int o  = (j >> 5) & 255;
        int ch = j >> 13;
        int gt = ch >> 1;
        int ci = (ch & 1)*32 + dk;
        int g  = gt / 9, tap = gt % 9;
        g_w2tc[j] = tf32r(adapt_w[(o*Cn + g*CGn + ci)*KKn + tap]);
    }
}

// GEMM core: warp tile 64px x 64oc, scalar conflict-free frag loads
#define MMA_CHUNK(Abuf, Bbuf)                                                  \
    _Pragma("unroll")                                                          \
    for (int ks = 0; ks < 4; ++ks) {                                           \
        const int k0 = ks*8;                                                   \
        uint32_t a[4][4];                                                      \
        _Pragma("unroll")                                                      \
        for (int ma = 0; ma < 4; ++ma) {                                       \
            const float* ap = &(Abuf)[(wm*64 + ma*16 + g)*LDA + k0 + t];       \
            a[ma][0] = __float_as_uint(ap[0]);                                 \
            a[ma][1] = __float_as_uint(ap[8*LDA]);                             \
            a[ma][2] = __float_as_uint(ap[4]);                                 \
            a[ma][3] = __float_as_uint(ap[8*LDA + 4]);                         \
        }                                                                      \
        _Pragma("unroll")                                                      \
        for (int na = 0; na < 8; ++na) {                                       \
            const float* bp = &(Bbuf)[(wn*64 + na*8 + g)*LDB + k0 + t];        \
            const uint32_t b0 = __float_as_uint(bp[0]);                        \
            const uint32_t b1 = __float_as_uint(bp[4]);                        \
            mma8(d[0][na], a[0], b0, b1);                                      \
            mma8(d[1][na], a[1], b0, b1);                                      \
            mma8(d[2][na], a[2], b0, b1);                                      \
            mma8(d[3][na], a[3], b0, b1);                                      \
        }                                                                      \
    }

// ---------------------------------------------------------------------------
// Kernel 3: conv3x3 via mma.sync tf32, 128px x 256oc CTA tile, fused heads
// Grid: (72, 2) = 144 CTAs (one wave). Block 256 (8 warps: 2m x 4n).
// ---------------------------------------------------------------------------
__global__ void __launch_bounds__(256, 1)
k_conv1_mma(const float* __restrict__ conv_b_,
            const float* __restrict__ loc_w,  const float* __restrict__ loc_b,
            const float* __restrict__ shape_w,const float* __restrict__ shape_b,
            const float* __restrict__ offset_w,
            float* __restrict__ out) {
    extern __shared__ __align__(128) char smem[];
    float* Asm = (float*)(smem + SM_A);
    float* Bsm = (float*)(smem + SM_B);
    float* red = (float*)(smem + SM_RED);
    float* shv = (float*)(smem + SM_SHV);
    const uint32_t sA = smem_u32(Asm), sB = smem_u32(Bsm);

    const int tid = threadIdx.x, wid = tid >> 5, lane = tid & 31;
    const int g = lane >> 2, t = lane & 3;
    const int wm = wid & 1, wn = wid >> 1;

    const int tt = blockIdx.x;
    const int b  = blockIdx.y;
    const int y0 = (tt / 6) * 8, x0 = (tt % 6) * 16;

    const int pB = tid >> 2, qS = tid & 3;   // staging base (phase adds 64)

    float d[4][8][4];
    #pragma unroll
    for (int i = 0; i < 4; ++i)
        #pragma unroll
        for (int j = 0; j < 8; ++j)
            #pragma unroll
            for (int k = 0; k < 4; ++k) d[i][j][k] = 0.f;

    #pragma unroll 1
    for (int c = 0; c < NCHUNK; ++c) {
        const int tap = c >> 3, cin0 = (c & 7) << 5;
        const int dy = tap/3 - 1, dx = tap%3 - 1;
        #pragma unroll
        for (int ph = 0; ph < 2; ++ph) {
            const int pS = ph*64 + pB;
            const int yy = y0 + (pS >> 4) + dy, xx = x0 + (pS & 15) + dx;
            const bool ok = (yy >= 0 && yy < Hn && xx >= 0 && xx < Wn);
            const float* src = ok
                ? &g_x[((size_t)((b*Hn + yy)*Wn + xx))*Cn + cin0 + qS*8] : g_x;
            const uint32_t nb = ok ? 16u : 0u;
            const uint32_t da = sA + (uint32_t)(pS*LDA + qS*8)*4;
            CPA16Z(da,      src,     nb);
            CPA16Z(da + 16, src + 4, nb);
        }
        {
            const uint32_t db = sB + (uint32_t)(tid*LDB)*4;
            const float* ws = &g_w1tc[(size_t)c*8192 + tid*32];
            #pragma unroll
            for (int q = 0; q < 8; ++q) CPA16(db + q*16, ws + q*4);
        }
        CPA_COMMIT();
        CPA_WAIT0();
        __syncthreads();
        MMA_CHUNK(Asm, Bsm);
        __syncthreads();
    }

    // ---- epilogue: bias + relu in place, head partials -----------------
    float P0[8], P1[8], P2[8];
    #pragma unroll
    for (int s = 0; s < 8; ++s) { P0[s] = 0.f; P1[s] = 0.f; P2[s] = 0.f; }

    #pragma unroll
    for (int ma = 0; ma < 4; ++ma)
        #pragma unroll
        for (int na = 0; na < 8; ++na)
            #pragma unroll
            for (int ci = 0; ci < 4; ++ci) {
                const int oc = wn*64 + na*8 + 2*t + (ci & 1);
                const int slot = ma*2 + (ci >> 1);
                float v = fmaxf(d[ma][na][ci] + conv_b_[oc], 0.f);
                d[ma][na][ci] = v;
                P0[slot] += v * loc_w[oc];
                P1[slot] += v * shape_w[oc];
                P2[slot] += v * shape_w[Cn + oc];
            }
    #pragma unroll
    for (int s = 0; s < 8; ++s) {
        P0[s] += __shfl_xor_sync(0xffffffffu, P0[s], 1);
        P0[s] += __shfl_xor_sync(0xffffffffu, P0[s], 2);
        P1[s] += __shfl_xor_sync(0xffffffffu, P1[s], 1);
        P1[s] += __shfl_xor_sync(0xffffffffu, P1[s], 2);
        P2[s] += __shfl_xor_sync(0xffffffffu, P2[s], 2);
        P2[s] += __shfl_xor_sync(0xffffffffu, P2[s], 1);
    }
    if (t == 0) {
        #pragma unroll
        for (int s = 0; s < 8; ++s) {
            const int row = wm*64 + (s >> 1)*16 + g + (s & 1)*8;
            red[0*512 + row*4 + wn] = P0[s];
            red[1*512 + row*4 + wn] = P1[s];
            red[2*512 + row*4 + wn] = P2[s];
        }
    }
    __syncthreads();

    if (tid < 128) {
        const int px = tid;
        float sl = 0.f, s0 = 0.f, s1 = 0.f;
        #pragma unroll
        for (int w = 0; w < 4; ++w) {
            sl += red[0*512 + px*4 + w];
            s0 += red[1*512 + px*4 + w];
            s1 += red[2*512 + px*4 + w];
        }
        const int y = y0 + (px >> 4), xg = x0 + (px & 15);
        const int pix = y*Wn + xg;
        out[OUT_LOC + b*HW + pix] = sl + loc_b[0];
        const float a0 = s0 + shape_b[0];
        const float a1 = s1 + shape_b[1];
        out[OUT_SHAPE + (b*2 + 0)*HW + pix] = a0;
        out[OUT_SHAPE + (b*2 + 1)*HW + pix] = a1;
        shv[px*2 + 0] = a0;
        shv[px*2 + 1] = a1;
    }
    __syncthreads();

    // offsets: 128 px x 72 ch
    for (int idx = tid; idx < 128*72; idx += 256) {
        const int p = idx / 72, j = idx % 72;
        const int y = y0 + (p >> 4), xg = x0 + (p & 15);
        float v = shv[p*2]*offset_w[j*2] + shv[p*2+1]*offset_w[j*2+1];
        g_off[((size_t)((b*Hn + y)*Wn + xg))*72 + j] = v;
    }

    // g_t: direct scattered STG.64 from accumulators
    #pragma unroll
    for (int ma = 0; ma < 4; ++ma) {
        const int row0 = wm*64 + ma*16 + g;
        const int pix0 = (b*Hn + y0 + (row0 >> 4))*Wn + x0 + (row0 & 15);
        const int row1 = row0 + 8;
        const int pix1 = (b*Hn + y0 + (row1 >> 4))*Wn + x0 + (row1 & 15);
        #pragma unroll
        for (int na = 0; na < 8; ++na) {
            const int col = wn*64 + na*8 + 2*t;
            *(float2*)&g_t[(size_t)pix0*Cn + col] =
                make_float2(d[ma][na][0], d[ma][na][1]);
            *(float2*)&g_t[(size_t)pix1*Cn + col] =
                make_float2(d[ma][na][2], d[ma][na][3]);
        }
    }
}

// ---------------------------------------------------------------------------
// Kernel 4: deformable conv via mma.sync tf32, 128px x 256oc, fused heads
// ---------------------------------------------------------------------------
__global__ void __launch_bounds__(256, 1)
k_deform_mma(const float* __restrict__ cls_w, const float* __restrict__ cls_b,
             const float* __restrict__ bbox_w, const float* __restrict__ bbox_b,
             float* __restrict__ out) {
    extern __shared__ __align__(128) char smem[];
    float* Asm = (float*)(smem + SM_A);
    float* Bsm = (float*)(smem + SM_B);
    float* red = (float*)(smem + SM_RED);
    const uint32_t sB = smem_u32(Bsm);

    const int tid = threadIdx.x, wid = tid >> 5, lane = tid & 31;
    const int g = lane >> 2, t = lane & 3;
    const int wm = wid & 1, wn = wid >> 1;

    const int tt = blockIdx.x;
    const int b  = blockIdx.y;
    const int y0 = (tt / 6) * 8, x0 = (tt % 6) * 16;

    const int pB = tid >> 2, qS = tid & 3;
    int   yP[2], xP[2], pixb[2];
    #pragma unroll
    for (int ph = 0; ph < 2; ++ph) {
        const int pS = ph*64 + pB;
        yP[ph] = y0 + (pS >> 4);
        xP[ph] = x0 + (pS & 15);
        pixb[ph] = (b*Hn + yP[ph])*Wn + xP[ph];
    }

    float d[4][8][4];
    #pragma unroll
    for (int i = 0; i < 4; ++i)
        #pragma unroll
        for (int j = 0; j < 8; ++j)
            #pragma unroll
            for (int k = 0; k < 4; ++k) d[i][j][k] = 0.f;

    int   ga[2][4];
    float gw[2][4];

    #pragma unroll 1
    for (int c = 0; c < NCHUNK; ++c) {
        if ((c & 1) == 0) {
            const int gt = c >> 1;
            const int gg = gt / 9, tap = gt - gg*9;
            const int dy = tap/3 - 1, dx = tap%3 - 1;
            #pragma unroll
            for (int ph = 0; ph < 2; ++ph) {
                const float2 off = *(const float2*)&g_off[(size_t)pixb[ph]*72 + gt*2];
                const float pyf = (float)(yP[ph] + dy) + off.x;
                const float pxf = (float)(xP[ph] + dx) + off.y;
                const float y0f = floorf(pyf), x0f = floorf(pxf);
                const float wy = pyf - y0f, wx = pxf - x0f;
                const int yi = (int)y0f, xi = (int)x0f;
                #pragma unroll
                for (int cy = 0; cy < 2; ++cy)
                    #pragma unroll
                    for (int cx = 0; cx < 2; ++cx) {
                        const int k = cy*2 + cx;
                        const int yc = yi + cy, xc = xi + cx;
                        const bool valid = (yc >= 0 && yc < Hn && xc >= 0 && xc < Wn);
                        const int ycc = min(max(yc, 0), Hn - 1);
                        const int xcc = min(max(xc, 0), Wn - 1);
                        const float wv = (cy ? wy : 1.f - wy) * (cx ? wx : 1.f - wx);
                        gw[ph][k] = valid ? wv : 0.f;
                        ga[ph][k] = ((b*Hn + ycc)*Wn + xcc)*Cn + gg*CGn;
                    }
            }
        }
        // stage B (cp.async) — overlaps the register gathers below
        {
            const uint32_t db = sB + (uint32_t)(tid*LDB)*4;
            const float* ws = &g_w2tc[(size_t)c*8192 + tid*32];
            #pragma unroll
            for (int q = 0; q < 8; ++q) CPA16(db + q*16, ws + q*4);
            CPA_COMMIT();
        }
        // gather + combine + STS, two 64-px phases
        const int chb = (c & 1)*32 + qS*8;
        #pragma unroll
        for (int ph = 0; ph < 2; ++ph) {
            float4 u[4][2];
            #pragma unroll
            for (int k = 0; k < 4; ++k) {
                u[k][0] = *(const float4*)&g_t[(size_t)ga[ph][k] + chb];
                u[k][1] = *(const float4*)&g_t[(size_t)ga[ph][k] + chb + 4];
            }
            const float w0 = gw[ph][0], w1 = gw[ph][1];
            const float w2 = gw[ph][2], w3 = gw[ph][3];
            float4 r0, r1;
            r0.x = tf32r(w0*u[0][0].x + w1*u[1][0].x + w2*u[2][0].x + w3*u[3][0].x);
            r0.y = tf32r(w0*u[0][0].y + w1*u[1][0].y + w2*u[2][0].y + w3*u[3][0].y);
            r0.z = tf32r(w0*u[0][0].z + w1*u[1][0].z + w2*u[2][0].z + w3*u[3][0].z);
            r0.w = tf32r(w0*u[0][0].w + w1*u[1][0].w + w2*u[2][0].w + w3*u[3][0].w);
            r1.x = tf32r(w0*u[0][1].x + w1*u[1][1].x + w2*u[2][1].x + w3*u[3][1].x);
            r1.y = tf32r(w0*u[0][1].y + w1*u[1][1].y + w2*u[2][1].y + w3*u[3][1].y);
            r1.z = tf32r(w0*u[0][1].z + w1*u[1][1].z + w2*u[2][1].z + w3*u[3][1].z);
            r1.w = tf32r(w0*u[0][1].w + w1*u[1][1].w + w2*u[2][1].w + w3*u[3][1].w);
            float* dst = &Asm[(ph*64 + pB)*LDA + qS*8];
            *(float4*)dst       = r0;
            *(float4*)(dst + 4) = r1;
        }
        CPA_WAIT0();
        __syncthreads();
        MMA_CHUNK(Asm, Bsm);
        __syncthreads();
    }

    // ---- epilogue: relu + cls/bbox head partials -----------------------
    float P[5][8];
    #pragma unroll
    for (int h = 0; h < 5; ++h)
        #pragma unroll
        for (int s = 0; s < 8; ++s) P[h][s] = 0.f;

    #pragma unroll
    for (int ma = 0; ma < 4; ++ma)
        #pragma unroll
        for (int na = 0; na < 8; ++na)
            #pragma unroll
            for (int ci = 0; ci < 4; ++ci) {
                const int oc = wn*64 + na*8 + 2*t + (ci & 1);
                const int slot = ma*2 + (ci >> 1);
                const float v = fmaxf(d[ma][na][ci], 0.f);
                P[0][slot] += v * cls_w[oc];
                P[1][slot] += v * bbox_w[oc];
                P[2][slot] += v * bbox_w[Cn + oc];
                P[3][slot] += v * bbox_w[2*Cn + oc];
                P[4][slot] += v * bbox_w[3*Cn + oc];
            }
    #pragma unroll
    for (int h = 0; h < 5; ++h)
        #pragma unroll
        for (int s = 0; s < 8; ++s) {
            P[h][s] += __shfl_xor_sync(0xffffffffu, P[h][s], 1);
            P[h][s] += __shfl_xor_sync(0xffffffffu, P[h][s], 2);
        }
    if (t == 0) {
        #pragma unroll
        for (int s = 0; s < 8; ++s) {
            const int row = wm*64 + (s >> 1)*16 + g + (s & 1)*8;
            #pragma unroll
            for (int h = 0; h < 5; ++h)
                red[h*512 + row*4 + wn] = P[h][s];
        }
    }
    __syncthreads();

    if (tid < 128) {
        const int px = tid;
        float s[5] = {0.f, 0.f, 0.f, 0.f, 0.f};
        #pragma unroll
        for (int h = 0; h < 5; ++h)
            #pragma unroll
            for (int w = 0; w < 4; ++w)
                s[h] += red[h*512 + px*4 + w];
        const int y = y0 + (px >> 4), xg = x0 + (px & 15);
        const int pix = y*Wn + xg;
        out[OUT_LOGITS + b*HW + pix]        = s[0] + cls_b[0];
        out[OUT_BBOX + (b*4 + 0)*HW + pix]  = s[1] + bbox_b[0];
        out[OUT_BBOX + (b*4 + 1)*HW + pix]  = s[2] + bbox_b[1];
        out[OUT_BBOX + (b*4 + 2)*HW + pix]  = s[3] + bbox_b[2];
        out[OUT_BBOX + (b*4 + 3)*HW + pix]  = s[4] + bbox_b[3];
    }
}

// ---------------------------------------------------------------------------
extern "C" void kernel_launch(void* const* d_in, const int* in_sizes, int n_in,
                              void* d_out, int out_size) {
    const float* feature  = (const float*)d_in[0];
    const float* conv_w   = (const float*)d_in[1];
    const float* conv_b   = (const float*)d_in[2];
    const float* loc_w    = (const float*)d_in[3];
    const float* loc_b    = (const float*)d_in[4];
    const float* shape_w  = (const float*)d_in[5];
    const float* shape_b  = (const float*)d_in[6];
    const float* offset_w = (const float*)d_in[7];
    const float* adapt_w  = (const float*)d_in[8];
    const float* cls_w    = (const float*)d_in[9];
    const float* cls_b    = (const float*)d_in[10];
    const float* bbox_w   = (const float*)d_in[11];
    const float* bbox_b   = (const float*)d_in[12];
    float* out = (float*)d_out;

    cudaFuncSetAttribute(k_conv1_mma,
        cudaFuncAttributeMaxDynamicSharedMemorySize, SM_TOTAL);
    cudaFuncSetAttribute(k_deform_mma,
        cudaFuncAttributeMaxDynamicSharedMemorySize, SM_TOTAL);

    k_transpose_feat<<<dim3(HW/32, Cn/32, Bn), dim3(32, 8)>>>(feature);
    k_prep_w<<<(2*KTOT*Cn + 255)/256, 256>>>(conv_w, adapt_w);
    k_conv1_mma<<<dim3(72, Bn), 256, SM_TOTAL>>>(conv_b, loc_w, loc_b,
                                                 shape_w, shape_b,
                                                 offset_w, out);
    k_deform_mma<<<dim3(72, Bn), 256, SM_TOTAL>>>(cls_w, cls_b,
                                                  bbox_w, bbox_b, out);
}

// round 9
// speedup vs baseline: 1.7144x; 1.0971x over previous
#include <cuda_runtime.h>
#include <math.h>
#include <stdint.h>

// Problem constants
#define Bn 2
#define Cn 256
#define Hn 96
#define Wn 96
#define HW (Hn*Wn)
#define CGn 64
#define KKn 9
#define KTOT 2304
#define NCHUNK 72           // K chunks of 32

// Output layout
#define OUT_LOGITS 0
#define OUT_BBOX   18432
#define OUT_SHAPE  92160
#define OUT_LOC    129024

// GEMM smem strides (floats) — 36: conflict-free scalar frag loads
#define LDA 36
#define LDB 36

// Dynamic smem byte offsets (double buffered)
#define SM_A0   0            // 128*36*4 = 18432
#define SM_A1   18432
#define SM_B0   36864        // 256*36*4 = 36864
#define SM_B1   73728
#define SM_RED  110592       // 5*512*4  = 10240
#define SM_SHV  120832       // 128*2*4  = 1024
#define SM_TOTAL 121856

// Scratch (device globals)
__device__ float g_x   [Bn*HW*Cn];     // feature NHWC (tf32-rounded)
__device__ float g_t   [Bn*HW*Cn];     // conv1 output NHWC (fp32)
__device__ float g_off [Bn*HW*72];
__device__ float g_w1tc[KTOT*Cn];      // [chunk][oc][32], tf32
__device__ float g_w2tc[KTOT*Cn];

// ---------------- helpers ---------------------------------------------------
__device__ __forceinline__ uint32_t smem_u32(const void* p) {
    uint32_t a;
    asm("{ .reg .u64 t; cvta.to.shared.u64 t, %1; cvt.u32.u64 %0, t; }"
        : "=r"(a) : "l"(p));
    return a;
}
__device__ __forceinline__ float tf32r(float x) {
    uint32_t u;
    asm("cvt.rna.tf32.f32 %0, %1;" : "=r"(u) : "f"(x));
    return __uint_as_float(u);
}
__device__ __forceinline__ void mma8(float* d, const uint32_t* a,
                                     uint32_t b0, uint32_t b1) {
    asm volatile(
        "mma.sync.aligned.m16n8k8.row.col.f32.tf32.tf32.f32 "
        "{%0,%1,%2,%3},{%4,%5,%6,%7},{%8,%9},{%0,%1,%2,%3};"
        : "+f"(d[0]), "+f"(d[1]), "+f"(d[2]), "+f"(d[3])
        : "r"(a[0]), "r"(a[1]), "r"(a[2]), "r"(a[3]), "r"(b0), "r"(b1));
}
#define CPA16(dst, src) \
    asm volatile("cp.async.ca.shared.global [%0], [%1], 16;" \
                 :: "r"(dst), "l"(src))
#define CPA16Z(dst, src, n) \
    asm volatile("cp.async.ca.shared.global [%0], [%1], 16, %2;" \
                 :: "r"(dst), "l"(src), "r"(n))
#define CPA_COMMIT() asm volatile("cp.async.commit_group;")
#define CPA_WAIT0()  asm volatile("cp.async.wait_group 0;")

// ---------------------------------------------------------------------------
// Kernel 1: NCHW -> NHWC transpose of feature, tf32-rounded
// ---------------------------------------------------------------------------
__global__ void k_transpose_feat(const float* __restrict__ x) {
    __shared__ float tile[32][33];
    int b  = blockIdx.z;
    int p0 = blockIdx.x * 32;
    int c0 = blockIdx.y * 32;
    int txi = threadIdx.x, tyi = threadIdx.y;  // 32 x 8
    #pragma unroll
    for (int s = 0; s < 32; s += 8)
        tile[tyi + s][txi] = x[(size_t)(b*Cn + c0 + tyi + s)*HW + p0 + txi];
    __syncthreads();
    #pragma unroll
    for (int s = 0; s < 32; s += 8)
        g_x[(size_t)(b*HW + p0 + tyi + s)*Cn + c0 + txi] = tf32r(tile[txi][tyi + s]);
}

// ---------------------------------------------------------------------------
// Kernel 2: weight re-layout into chunked [chunk][oc][32] tf32 tiles
// ---------------------------------------------------------------------------
__global__ void k_prep_w(const float* __restrict__ conv_w,
                         const float* __restrict__ adapt_w) {
    const int n = KTOT*Cn;
    int idx = blockIdx.x * blockDim.x + threadIdx.x;
    if (idx < n) {
        int dk = idx & 31;
        int o  = (idx >> 5) & 255;
        int ch = idx >> 13;
        int tap = ch >> 3;
        int c   = (ch & 7)*32 + dk;
        g_w1tc[idx] = tf32r(conv_w[(o*Cn + c)*KKn + tap]);
    } else if (idx < 2*n) {
        int j  = idx - n;
        int dk = j & 31;
        int o  = (j >> 5) & 255;
        int ch = j >> 13;
        int gt = ch >> 1;
        int ci = (ch & 1)*32 + dk;
        int g  = gt / 9, tap = gt % 9;
        g_w2tc[j] = tf32r(adapt_w[(o*Cn + g*CGn + ci)*KKn + tap]);
    }
}

// One k-step of the 128x256 CTA tile (warp tile 64px x 64oc)
#define MMA_KSTEP(Abuf, Bbuf, ks) {                                            \
    const int k0 = (ks)*8;                                                     \
    uint32_t a[4][4];                                                          \
    _Pragma("unroll")                                                          \
    for (int ma = 0; ma < 4; ++ma) {                                           \
        const float* ap = &(Abuf)[(wm*64 + ma*16 + g)*LDA + k0 + t];           \
        a[ma][0] = __float_as_uint(ap[0]);                                     \
        a[ma][1] = __float_as_uint(ap[8*LDA]);                                 \
        a[ma][2] = __float_as_uint(ap[4]);                                     \
        a[ma][3] = __float_as_uint(ap[8*LDA + 4]);                             \
    }                                                                          \
    _Pragma("unroll")                                                          \
    for (int na = 0; na < 8; ++na) {                                           \
        const float* bp = &(Bbuf)[(wn*64 + na*8 + g)*LDB + k0 + t];            \
        const uint32_t b0 = __float_as_uint(bp[0]);                            \
        const uint32_t b1 = __float_as_uint(bp[4]);                            \
        mma8(d[0][na], a[0], b0, b1);                                          \
        mma8(d[1][na], a[1], b0, b1);                                          \
        mma8(d[2][na], a[2], b0, b1);                                          \
        mma8(d[3][na], a[3], b0, b1);                                          \
    }                                                                          \
}

#define MMA_CHUNK(Abuf, Bbuf) \
    MMA_KSTEP(Abuf, Bbuf, 0) MMA_KSTEP(Abuf, Bbuf, 1) \
    MMA_KSTEP(Abuf, Bbuf, 2) MMA_KSTEP(Abuf, Bbuf, 3)

// ---------------------------------------------------------------------------
// Kernel 3: conv3x3 via mma.sync tf32, 128x256 tile, double-buffered pipeline
// ---------------------------------------------------------------------------
__global__ void __launch_bounds__(256, 1)
k_conv1_mma(const float* __restrict__ conv_b_,
            const float* __restrict__ loc_w,  const float* __restrict__ loc_b,
            const float* __restrict__ shape_w,const float* __restrict__ shape_b,
            const float* __restrict__ offset_w,
            float* __restrict__ out) {
    extern __shared__ __align__(128) char smem[];
    float* Asm0 = (float*)(smem + SM_A0);
    float* Asm1 = (float*)(smem + SM_A1);
    float* Bsm0 = (float*)(smem + SM_B0);
    float* Bsm1 = (float*)(smem + SM_B1);
    float* red  = (float*)(smem + SM_RED);
    float* shv  = (float*)(smem + SM_SHV);

    const int tid = threadIdx.x, wid = tid >> 5, lane = tid & 31;
    const int g = lane >> 2, t = lane & 3;
    const int wm = wid & 1, wn = wid >> 1;

    const int tt = blockIdx.x;
    const int b  = blockIdx.y;
    const int y0 = (tt / 6) * 8, x0 = (tt % 6) * 16;

    const int pB = tid >> 2, qS = tid & 3;

    float d[4][8][4];
    #pragma unroll
    for (int i = 0; i < 4; ++i)
        #pragma unroll
        for (int j = 0; j < 8; ++j)
            #pragma unroll
            for (int k = 0; k < 4; ++k) d[i][j][k] = 0.f;

    const uint32_t daOff = (uint32_t)(pB*LDA + qS*8)*4;
    const uint32_t dbOff = (uint32_t)(tid*LDB)*4;
    const uint32_t da0 = smem_u32(Asm0) + daOff, da1 = smem_u32(Asm1) + daOff;
    const uint32_t db0 = smem_u32(Bsm0) + dbOff, db1 = smem_u32(Bsm1) + dbOff;

    auto stage = [&](int c, uint32_t da, uint32_t db) {
        const int tap = c >> 3, cin0 = (c & 7) << 5;
        const int dy = tap/3 - 1, dx = tap%3 - 1;
        #pragma unroll
        for (int ph = 0; ph < 2; ++ph) {
            const int pS = ph*64 + pB;
            const int yy = y0 + (pS >> 4) + dy, xx = x0 + (pS & 15) + dx;
            const bool ok = (yy >= 0 && yy < Hn && xx >= 0 && xx < Wn);
            const float* src = ok
                ? &g_x[((size_t)((b*Hn + yy)*Wn + xx))*Cn + cin0 + qS*8] : g_x;
            const uint32_t nb = ok ? 16u : 0u;
            CPA16Z(da + (uint32_t)(ph*64*LDA)*4,      src,     nb);
            CPA16Z(da + (uint32_t)(ph*64*LDA)*4 + 16, src + 4, nb);
        }
        const float* ws = &g_w1tc[(size_t)c*8192 + tid*32];
        #pragma unroll
        for (int q = 0; q < 8; ++q) CPA16(db + q*16, ws + q*4);
        CPA_COMMIT();
    };

    stage(0, da0, db0);
    CPA_WAIT0();
    __syncthreads();

    #pragma unroll 1
    for (int c = 0; c < NCHUNK; c += 2) {
        if (c + 1 < NCHUNK) stage(c + 1, da1, db1);
        MMA_CHUNK(Asm0, Bsm0);
        CPA_WAIT0();
        __syncthreads();
        if (c + 2 < NCHUNK) stage(c + 2, da0, db0);
        MMA_CHUNK(Asm1, Bsm1);
        CPA_WAIT0();
        __syncthreads();
    }

    // ---- epilogue: bias + relu in place, head partials -----------------
    float P0[8], P1[8], P2[8];
    #pragma unroll
    for (int s = 0; s < 8; ++s) { P0[s] = 0.f; P1[s] = 0.f; P2[s] = 0.f; }

    #pragma unroll
    for (int ma = 0; ma < 4; ++ma)
        #pragma unroll
        for (int na = 0; na < 8; ++na)
            #pragma unroll
            for (int ci = 0; ci < 4; ++ci) {
                const int oc = wn*64 + na*8 + 2*t + (ci & 1);
                const int slot = ma*2 + (ci >> 1);
                float v = fmaxf(d[ma][na][ci] + conv_b_[oc], 0.f);
                d[ma][na][ci] = v;
                P0[slot] += v * loc_w[oc];
                P1[slot] += v * shape_w[oc];
                P2[slot] += v * shape_w[Cn + oc];
            }
    #pragma unroll
    for (int s = 0; s < 8; ++s) {
        P0[s] += __shfl_xor_sync(0xffffffffu, P0[s], 1);
        P0[s] += __shfl_xor_sync(0xffffffffu, P0[s], 2);
        P1[s] += __shfl_xor_sync(0xffffffffu, P1[s], 1);
        P1[s] += __shfl_xor_sync(0xffffffffu, P1[s], 2);
        P2[s] += __shfl_xor_sync(0xffffffffu, P2[s], 2);
        P2[s] += __shfl_xor_sync(0xffffffffu, P2[s], 1);
    }
    if (t == 0) {
        #pragma unroll
        for (int s = 0; s < 8; ++s) {
            const int row = wm*64 + (s >> 1)*16 + g + (s & 1)*8;
            red[0*512 + row*4 + wn] = P0[s];
            red[1*512 + row*4 + wn] = P1[s];
            red[2*512 + row*4 + wn] = P2[s];
        }
    }
    __syncthreads();

    if (tid < 128) {
        const int px = tid;
        float sl = 0.f, s0 = 0.f, s1 = 0.f;
        #pragma unroll
        for (int w = 0; w < 4; ++w) {
            sl += red[0*512 + px*4 + w];
            s0 += red[1*512 + px*4 + w];
            s1 += red[2*512 + px*4 + w];
        }
        const int y = y0 + (px >> 4), xg = x0 + (px & 15);
        const int pix = y*Wn + xg;
        out[OUT_LOC + b*HW + pix] = sl + loc_b[0];
        const float a0 = s0 + shape_b[0];
        const float a1 = s1 + shape_b[1];
        out[OUT_SHAPE + (b*2 + 0)*HW + pix] = a0;
        out[OUT_SHAPE + (b*2 + 1)*HW + pix] = a1;
        shv[px*2 + 0] = a0;
        shv[px*2 + 1] = a1;
    }
    __syncthreads();

    // offsets: 128 px x 72 ch
    for (int idx = tid; idx < 128*72; idx += 256) {
        const int p = idx / 72, j = idx % 72;
        const int y = y0 + (p >> 4), xg = x0 + (p & 15);
        float v = shv[p*2]*offset_w[j*2] + shv[p*2+1]*offset_w[j*2+1];
        g_off[((size_t)((b*Hn + y)*Wn + xg))*72 + j] = v;
    }

    // g_t: direct scattered STG.64 from accumulators
    #pragma unroll
    for (int ma = 0; ma < 4; ++ma) {
        const int row0 = wm*64 + ma*16 + g;
        const int pix0 = (b*Hn + y0 + (row0 >> 4))*Wn + x0 + (row0 & 15);
        const int row1 = row0 + 8;
        const int pix1 = (b*Hn + y0 + (row1 >> 4))*Wn + x0 + (row1 & 15);
        #pragma unroll
        for (int na = 0; na < 8; ++na) {
            const int col = wn*64 + na*8 + 2*t;
            *(float2*)&g_t[(size_t)pix0*Cn + col] =
                make_float2(d[ma][na][0], d[ma][na][1]);
            *(float2*)&g_t[(size_t)pix1*Cn + col] =
                make_float2(d[ma][na][2], d[ma][na][3]);
        }
    }
}

// ---------------------------------------------------------------------------
// Kernel 4: deformable conv, 128x256 tile, interleaved gather pipeline
// ---------------------------------------------------------------------------
__global__ void __launch_bounds__(256, 1)
k_deform_mma(const float* __restrict__ cls_w, const float* __restrict__ cls_b,
             const float* __restrict__ bbox_w, const float* __restrict__ bbox_b,
             float* __restrict__ out) {
    extern __shared__ __align__(128) char smem[];
    float* Asm0 = (float*)(smem + SM_A0);
    float* Asm1 = (float*)(smem + SM_A1);
    float* Bsm0 = (float*)(smem + SM_B0);
    float* Bsm1 = (float*)(smem + SM_B1);
    float* red  = (float*)(smem + SM_RED);

    const int tid = threadIdx.x, wid = tid >> 5, lane = tid & 31;
    const int g = lane >> 2, t = lane & 3;
    const int wm = wid & 1, wn = wid >> 1;

    const int tt = blockIdx.x;
    const int b  = blockIdx.y;
    const int y0 = (tt / 6) * 8, x0 = (tt % 6) * 16;

    const int pB = tid >> 2, qS = tid & 3;
    int   yP[2], xP[2], pixb[2];
    #pragma unroll
    for (int ph = 0; ph < 2; ++ph) {
        const int pS = ph*64 + pB;
        yP[ph] = y0 + (pS >> 4);
        xP[ph] = x0 + (pS & 15);
        pixb[ph] = (b*Hn + yP[ph])*Wn + xP[ph];
    }

    float d[4][8][4];
    #pragma unroll
    for (int i = 0; i < 4; ++i)
        #pragma unroll
        for (int j = 0; j < 8; ++j)
            #pragma unroll
            for (int k = 0; k < 4; ++k) d[i][j][k] = 0.f;

    const uint32_t dbOff = (uint32_t)(tid*LDB)*4;
    const uint32_t db0 = smem_u32(Bsm0) + dbOff, db1 = smem_u32(Bsm1) + dbOff;

    int    ga[2][4];
    float  gw[2][4];
    float4 u[4];            // transient: one float4 per corner
    float2 offA, offB;      // prefetched offsets for next gt (both phases)

    auto calc_meta = [&](int gt, float2 o0, float2 o1) {
        const int gg = gt / 9, tap = gt - gg*9;
        const int dy = tap/3 - 1, dx = tap%3 - 1;
        #pragma unroll
        for (int ph = 0; ph < 2; ++ph) {
            const float2 off = ph ? o1 : o0;
            const float pyf = (float)(yP[ph] + dy) + off.x;
            const float pxf = (float)(xP[ph] + dx) + off.y;
            const float y0f = floorf(pyf), x0f = floorf(pxf);
            const float wy = pyf - y0f, wx = pxf - x0f;
            const int yi = (int)y0f, xi = (int)x0f;
            #pragma unroll
            for (int cy = 0; cy < 2; ++cy)
                #pragma unroll
                for (int cx = 0; cx < 2; ++cx) {
                    const int k = cy*2 + cx;
                    const int yc = yi + cy, xc = xi + cx;
                    const bool valid = (yc >= 0 && yc < Hn && xc >= 0 && xc < Wn);
                    const int ycc = min(max(yc, 0), Hn - 1);
                    const int xcc = min(max(xc, 0), Wn - 1);
                    const float wv = (cy ? wy : 1.f - wy) * (cx ? wx : 1.f - wx);
                    gw[ph][k] = valid ? wv : 0.f;
                    ga[ph][k] = ((b*Hn + ycc)*Wn + xcc)*Cn + gg*CGn;
                }
        }
    };

// sub-stage: sub = ph*2 + h; gathers one float4 per corner for chunk cc
#define GATHER_SUB(cc, sub) {                                                  \
    const int _ph = (sub) >> 1, _h = (sub) & 1;                                \
    const int _chb = ((cc) & 1)*32 + qS*8 + _h*4;                              \
    u[0] = *(const float4*)&g_t[(size_t)ga[_ph][0] + _chb];                    \
    u[1] = *(const float4*)&g_t[(size_t)ga[_ph][1] + _chb];                    \
    u[2] = *(const float4*)&g_t[(size_t)ga[_ph][2] + _chb];                    \
    u[3] = *(const float4*)&g_t[(size_t)ga[_ph][3] + _chb];                    \
}
#define COMBINE_STS(sub, Abuf) {                                               \
    const int _ph = (sub) >> 1, _h = (sub) & 1;                                \
    const float w0 = gw[_ph][0], w1 = gw[_ph][1];                              \
    const float w2 = gw[_ph][2], w3 = gw[_ph][3];                              \
    float4 r;                                                                  \
    r.x = tf32r(w0*u[0].x + w1*u[1].x + w2*u[2].x + w3*u[3].x);                \
    r.y = tf32r(w0*u[0].y + w1*u[1].y + w2*u[2].y + w3*u[3].y);                \
    r.z = tf32r(w0*u[0].z + w1*u[1].z + w2*u[2].z + w3*u[3].z);                \
    r.w = tf32r(w0*u[0].w + w1*u[1].w + w2*u[2].w + w3*u[3].w);                \
    *(float4*)&(Abuf)[(_ph*64 + pB)*LDA + qS*8 + _h*4] = r;                    \
}
#define STAGE_B(cc, db) {                                                      \
    const float* ws = &g_w2tc[(size_t)(cc)*8192 + tid*32];                     \
    _Pragma("unroll")                                                          \
    for (int q = 0; q < 8; ++q) CPA16((db) + q*16, ws + q*4);                  \
    CPA_COMMIT();                                                              \
}
// MMA over chunk in bufX while staging chunk cn into bufY (interleaved)
#define DEFORM_STEP(AX, BX, cn, AY, dbY, hasnext) {                            \
    if (hasnext) { STAGE_B(cn, dbY); GATHER_SUB(cn, 0); }                      \
    MMA_KSTEP(AX, BX, 0)                                                       \
    if (hasnext) { COMBINE_STS(0, AY); GATHER_SUB(cn, 1); }                    \
    MMA_KSTEP(AX, BX, 1)                                                       \
    if (hasnext) { COMBINE_STS(1, AY); GATHER_SUB(cn, 2); }                    \
    MMA_KSTEP(AX, BX, 2)                                                       \
    if (hasnext) { COMBINE_STS(2, AY); GATHER_SUB(cn, 3); }                    \
    MMA_KSTEP(AX, BX, 3)                                                       \
    if (hasnext) { COMBINE_STS(3, AY); }                                       \
    CPA_WAIT0();                                                               \
    __syncthreads();                                                           \
}

    // prologue: meta gt0, stage chunk 0 -> buf0 serially, prefetch gt1 offsets
    offA = *(const float2*)&g_off[(size_t)pixb[0]*72];
    offB = *(const float2*)&g_off[(size_t)pixb[1]*72];
    calc_meta(0, offA, offB);
    offA = *(const float2*)&g_off[(size_t)pixb[0]*72 + 2];
    offB = *(const float2*)&g_off[(size_t)pixb[1]*72 + 2];
    STAGE_B(0, db0);
    GATHER_SUB(0, 0); COMBINE_STS(0, Asm0);
    GATHER_SUB(0, 1); COMBINE_STS(1, Asm0);
    GATHER_SUB(0, 2); COMBINE_STS(2, Asm0);
    GATHER_SUB(0, 3); COMBINE_STS(3, Asm0);
    CPA_WAIT0();
    __syncthreads();

    #pragma unroll 1
    for (int c = 0; c < NCHUNK; c += 2) {
        // chunk c in buf0; stage c+1 (odd, same gt) into buf1
        DEFORM_STEP(Asm0, Bsm0, c + 1, Asm1, db1, (c + 1 < NCHUNK))
        // chunk c+2 is a new gt: compute meta from prefetched offsets
        if (c + 2 < NCHUNK) {
            const int gt = (c + 2) >> 1;
            calc_meta(gt, offA, offB);
            if (gt + 1 < 36) {
                offA = *(const float2*)&g_off[(size_t)pixb[0]*72 + (gt + 1)*2];
                offB = *(const float2*)&g_off[(size_t)pixb[1]*72 + (gt + 1)*2];
            }
        }
        // chunk c+1 in buf1; stage c+2 into buf0
        DEFORM_STEP(Asm1, Bsm1, c + 2, Asm0, db0, (c + 2 < NCHUNK))
    }

    // ---- epilogue: relu + cls/bbox head partials -----------------------
    float P[5][8];
    #pragma unroll
    for (int h = 0; h < 5; ++h)
        #pragma unroll
        for (int s = 0; s < 8; ++s) P[h][s] = 0.f;

    #pragma unroll
    for (int ma = 0; ma < 4; ++ma)
        #pragma unroll
        for (int na = 0; na < 8; ++na)
            #pragma unroll
            for (int ci = 0; ci < 4; ++ci) {
                const int oc = wn*64 + na*8 + 2*t + (ci & 1);
                const int slot = ma*2 + (ci >> 1);
                const float v = fmaxf(d[ma][na][ci], 0.f);
                P[0][slot] += v * cls_w[oc];
                P[1][slot] += v * bbox_w[oc];
                P[2][slot] += v * bbox_w[Cn + oc];
                P[3][slot] += v * bbox_w[2*Cn + oc];
                P[4][slot] += v * bbox_w[3*Cn + oc];
            }
    #pragma unroll
    for (int h = 0; h < 5; ++h)
        #pragma unroll
        for (int s = 0; s < 8; ++s) {
            P[h][s] += __shfl_xor_sync(0xffffffffu, P[h][s], 1);
            P[h][s] += __shfl_xor_sync(0xffffffffu, P[h][s], 2);
        }
    if (t == 0) {
        #pragma unroll
        for (int s = 0; s < 8; ++s) {
            const int row = wm*64 + (s >> 1)*16 + g + (s & 1)*8;
            #pragma unroll
            for (int h = 0; h < 5; ++h)
                red[h*512 + row*4 + wn] = P[h][s];
        }
    }
    __syncthreads();

    if (tid < 128) {
        const int px = tid;
        float s[5] = {0.f, 0.f, 0.f, 0.f, 0.f};
        #pragma unroll
        for (int h = 0; h < 5; ++h)
            #pragma unroll
            for (int w = 0; w < 4; ++w)
                s[h] += red[h*512 + px*4 + w];
        const int y = y0 + (px >> 4), xg = x0 + (px & 15);
        const int pix = y*Wn + xg;
        out[OUT_LOGITS + b*HW + pix]        = s[0] + cls_b[0];
        out[OUT_BBOX + (b*4 + 0)*HW + pix]  = s[1] + bbox_b[0];
        out[OUT_BBOX + (b*4 + 1)*HW + pix]  = s[2] + bbox_b[1];
        out[OUT_BBOX + (b*4 + 2)*HW + pix]  = s[3] + bbox_b[2];
        out[OUT_BBOX + (b*4 + 3)*HW + pix]  = s[4] + bbox_b[3];
    }
}

// ---------------------------------------------------------------------------
extern "C" void kernel_launch(void* const* d_in, const int* in_sizes, int n_in,
                              void* d_out, int out_size) {
    const float* feature  = (const float*)d_in[0];
    const float* conv_w   = (const float*)d_in[1];
    const float* conv_b   = (const float*)d_in[2];
    const float* loc_w    = (const float*)d_in[3];
    const float* loc_b    = (const float*)d_in[4];
    const float* shape_w  = (const float*)d_in[5];
    const float* shape_b  = (const float*)d_in[6];
    const float* offset_w = (const float*)d_in[7];
    const float* adapt_w  = (const float*)d_in[8];
    const float* cls_w    = (const float*)d_in[9];
    const float* cls_b    = (const float*)d_in[10];
    const float* bbox_w   = (const float*)d_in[11];
    const float* bbox_b   = (const float*)d_in[12];
    float* out = (float*)d_out;

    cudaFuncSetAttribute(k_conv1_mma,
        cudaFuncAttributeMaxDynamicSharedMemorySize, SM_TOTAL);
    cudaFuncSetAttribute(k_deform_mma,
        cudaFuncAttributeMaxDynamicSharedMemorySize, SM_TOTAL);

    k_transpose_feat<<<dim3(HW/32, Cn/32, Bn), dim3(32, 8)>>>(feature);
    k_prep_w<<<(2*KTOT*Cn + 255)/256, 256>>>(conv_w, adapt_w);
    k_conv1_mma<<<dim3(72, Bn), 256, SM_TOTAL>>>(conv_b, loc_w, loc_b,
                                                 shape_w, shape_b,
                                                 offset_w, out);
    k_deform_mma<<<dim3(72, Bn), 256, SM_TOTAL>>>(cls_w, cls_b,
                                                  bbox_w, bbox_b, out);
}

// round 10
// speedup vs baseline: 3.3767x; 1.9696x over previous
#include <cuda_runtime.h>
#include <cuda_fp16.h>
#include <math.h>
#include <stdint.h>

// Problem constants
#define Bn 2
#define Cn 256
#define Hn 96
#define Wn 96
#define HW (Hn*Wn)
#define CGn 64
#define KKn 9
#define KTOT 2304
#define NCHUNK 72           // K chunks of 32

// Output layout
#define OUT_LOGITS 0
#define OUT_BBOX   18432
#define OUT_SHAPE  92160
#define OUT_LOC    129024

// smem strides in HALVES — 40: (20g+t) mod 32 is a permutation -> conflict-free
#define LDAh 40
#define LDBh 40

// Dynamic smem byte offsets (double buffered, fp16 tiles)
#define SM_A0   0            // 128*40*2 = 10240
#define SM_A1   10240
#define SM_B0   20480        // 256*40*2 = 20480
#define SM_B1   40960
#define SM_RED  61440        // 5*512*4  = 10240
#define SM_SHV  71680        // 128*2*4  = 1024
#define SM_TOTAL 72704

// Scratch (device globals)
__device__ __half g_x  [Bn*HW*Cn];     // feature NHWC, fp16
__device__ __half g_t  [Bn*HW*Cn];     // conv1 output NHWC, fp16
__device__ float  g_off[Bn*HW*72];
__device__ __half g_w1h[KTOT*Cn];      // [chunk][oc][32], fp16
__device__ __half g_w2h[KTOT*Cn];

// ---------------- helpers ---------------------------------------------------
__device__ __forceinline__ uint32_t smem_u32(const void* p) {
    uint32_t a;
    asm("{ .reg .u64 t; cvta.to.shared.u64 t, %1; cvt.u32.u64 %0, t; }"
        : "=r"(a) : "l"(p));
    return a;
}
__device__ __forceinline__ void mma16(float* d, const uint32_t* a,
                                      uint32_t b0, uint32_t b1) {
    asm volatile(
        "mma.sync.aligned.m16n8k16.row.col.f32.f16.f16.f32 "
        "{%0,%1,%2,%3},{%4,%5,%6,%7},{%8,%9},{%0,%1,%2,%3};"
        : "+f"(d[0]), "+f"(d[1]), "+f"(d[2]), "+f"(d[3])
        : "r"(a[0]), "r"(a[1]), "r"(a[2]), "r"(a[3]), "r"(b0), "r"(b1));
}
#define CPA16(dst, src) \
    asm volatile("cp.async.ca.shared.global [%0], [%1], 16;" \
                 :: "r"(dst), "l"(src))
#define CPA16Z(dst, src, n) \
    asm volatile("cp.async.ca.shared.global [%0], [%1], 16, %2;" \
                 :: "r"(dst), "l"(src), "r"(n))
#define CPA_COMMIT() asm volatile("cp.async.commit_group;")
#define CPA_WAIT0()  asm volatile("cp.async.wait_group 0;")

// ---------------------------------------------------------------------------
// Kernel 1: NCHW -> NHWC transpose of feature, to fp16
// ---------------------------------------------------------------------------
__global__ void k_transpose_feat(const float* __restrict__ x) {
    __shared__ float tile[32][33];
    int b  = blockIdx.z;
    int p0 = blockIdx.x * 32;
    int c0 = blockIdx.y * 32;
    int txi = threadIdx.x, tyi = threadIdx.y;  // 32 x 8
    #pragma unroll
    for (int s = 0; s < 32; s += 8)
        tile[tyi + s][txi] = x[(size_t)(b*Cn + c0 + tyi + s)*HW + p0 + txi];
    __syncthreads();
    #pragma unroll
    for (int s = 0; s < 32; s += 8)
        g_x[(size_t)(b*HW + p0 + tyi + s)*Cn + c0 + txi] =
            __float2half(tile[txi][tyi + s]);
}

// ---------------------------------------------------------------------------
// Kernel 2: weight re-layout into chunked [chunk][oc][32] fp16 tiles
// ---------------------------------------------------------------------------
__global__ void k_prep_w(const float* __restrict__ conv_w,
                         const float* __restrict__ adapt_w) {
    const int n = KTOT*Cn;
    int idx = blockIdx.x * blockDim.x + threadIdx.x;
    if (idx < n) {
        int dk = idx & 31;
        int o  = (idx >> 5) & 255;
        int ch = idx >> 13;
        int tap = ch >> 3;
        int c   = (ch & 7)*32 + dk;
        g_w1h[idx] = __float2half(conv_w[(o*Cn + c)*KKn + tap]);
    } else if (idx < 2*n) {
        int j  = idx - n;
        int dk = j & 31;
        int o  = (j >> 5) & 255;
        int ch = j >> 13;
        int gt = ch >> 1;
        int ci = (ch & 1)*32 + dk;
        int g  = gt / 9, tap = gt % 9;
        g_w2h[j] = __float2half(adapt_w[(o*Cn + g*CGn + ci)*KKn + tap]);
    }
}

// One k16-step of the 128x256 tile (warp tile 64px x 64oc)
#define MMA_KSTEP(Abuf, Bbuf, ks) {                                            \
    const int k0 = (ks)*16;                                                    \
    uint32_t a[4][4];                                                          \
    _Pragma("unroll")                                                          \
    for (int ma = 0; ma < 4; ++ma) {                                           \
        const __half* ap = &(Abuf)[(wm*64 + ma*16 + g)*LDAh + k0 + 2*t];       \
        a[ma][0] = *(const uint32_t*)(ap);                                     \
        a[ma][1] = *(const uint32_t*)(ap + 8*LDAh);                            \
        a[ma][2] = *(const uint32_t*)(ap + 8);                                 \
        a[ma][3] = *(const uint32_t*)(ap + 8*LDAh + 8);                        \
    }                                                                          \
    _Pragma("unroll")                                                          \
    for (int na = 0; na < 8; ++na) {                                           \
        const __half* bp = &(Bbuf)[(wn*64 + na*8 + g)*LDBh + k0 + 2*t];        \
        const uint32_t b0 = *(const uint32_t*)(bp);                            \
        const uint32_t b1 = *(const uint32_t*)(bp + 8);                        \
        mma16(d[0][na], a[0], b0, b1);                                         \
        mma16(d[1][na], a[1], b0, b1);                                         \
        mma16(d[2][na], a[2], b0, b1);                                         \
        mma16(d[3][na], a[3], b0, b1);                                         \
    }                                                                          \
}

#define MMA_CHUNK(Abuf, Bbuf) MMA_KSTEP(Abuf, Bbuf, 0) MMA_KSTEP(Abuf, Bbuf, 1)

// ---------------------------------------------------------------------------
// Kernel 3: conv3x3 via mma.sync fp16, 128x256 tile, double-buffered
// ---------------------------------------------------------------------------
__global__ void __launch_bounds__(256, 1)
k_conv1_mma(const float* __restrict__ conv_b_,
            const float* __restrict__ loc_w,  const float* __restrict__ loc_b,
            const float* __restrict__ shape_w,const float* __restrict__ shape_b,
            const float* __restrict__ offset_w,
            float* __restrict__ out) {
    extern __shared__ __align__(128) char smem[];
    __half* Asm0 = (__half*)(smem + SM_A0);
    __half* Asm1 = (__half*)(smem + SM_A1);
    __half* Bsm0 = (__half*)(smem + SM_B0);
    __half* Bsm1 = (__half*)(smem + SM_B1);
    float*  red  = (float*)(smem + SM_RED);
    float*  shv  = (float*)(smem + SM_SHV);

    const int tid = threadIdx.x, wid = tid >> 5, lane = tid & 31;
    const int g = lane >> 2, t = lane & 3;
    const int wm = wid & 1, wn = wid >> 1;

    const int tt = blockIdx.x;
    const int b  = blockIdx.y;
    const int y0 = (tt / 6) * 8, x0 = (tt % 6) * 16;

    const int pB = tid >> 2, qS = tid & 3;

    float d[4][8][4];
    #pragma unroll
    for (int i = 0; i < 4; ++i)
        #pragma unroll
        for (int j = 0; j < 8; ++j)
            #pragma unroll
            for (int k = 0; k < 4; ++k) d[i][j][k] = 0.f;

    const uint32_t daOff = (uint32_t)(pB*LDAh + qS*8)*2;
    const uint32_t dbOff = (uint32_t)(tid*LDBh)*2;
    const uint32_t da0 = smem_u32(Asm0) + daOff, da1 = smem_u32(Asm1) + daOff;
    const uint32_t db0 = smem_u32(Bsm0) + dbOff, db1 = smem_u32(Bsm1) + dbOff;

    auto stage = [&](int c, uint32_t da, uint32_t db) {
        const int tap = c >> 3, cin0 = (c & 7) << 5;
        const int dy = tap/3 - 1, dx = tap%3 - 1;
        #pragma unroll
        for (int ph = 0; ph < 2; ++ph) {
            const int pS = ph*64 + pB;
            const int yy = y0 + (pS >> 4) + dy, xx = x0 + (pS & 15) + dx;
            const bool ok = (yy >= 0 && yy < Hn && xx >= 0 && xx < Wn);
            const __half* src = ok
                ? &g_x[((size_t)((b*Hn + yy)*Wn + xx))*Cn + cin0 + qS*8] : g_x;
            const uint32_t nb = ok ? 16u : 0u;
            CPA16Z(da + (uint32_t)(ph*64*LDAh)*2, src, nb);
        }
        const __half* ws = &g_w1h[(size_t)c*8192 + tid*32];
        #pragma unroll
        for (int q = 0; q < 4; ++q) CPA16(db + q*16, ws + q*8);
        CPA_COMMIT();
    };

    stage(0, da0, db0);
    CPA_WAIT0();
    __syncthreads();

    #pragma unroll 1
    for (int c = 0; c < NCHUNK; c += 2) {
        if (c + 1 < NCHUNK) stage(c + 1, da1, db1);
        MMA_CHUNK(Asm0, Bsm0);
        CPA_WAIT0();
        __syncthreads();
        if (c + 2 < NCHUNK) stage(c + 2, da0, db0);
        MMA_CHUNK(Asm1, Bsm1);
        CPA_WAIT0();
        __syncthreads();
    }

    // ---- epilogue: bias + relu in place, head partials -----------------
    float P0[8], P1[8], P2[8];
    #pragma unroll
    for (int s = 0; s < 8; ++s) { P0[s] = 0.f; P1[s] = 0.f; P2[s] = 0.f; }

    #pragma unroll
    for (int ma = 0; ma < 4; ++ma)
        #pragma unroll
        for (int na = 0; na < 8; ++na)
            #pragma unroll
            for (int ci = 0; ci < 4; ++ci) {
                const int oc = wn*64 + na*8 + 2*t + (ci & 1);
                const int slot = ma*2 + (ci >> 1);
                float v = fmaxf(d[ma][na][ci] + conv_b_[oc], 0.f);
                d[ma][na][ci] = v;
                P0[slot] += v * loc_w[oc];
                P1[slot] += v * shape_w[oc];
                P2[slot] += v * shape_w[Cn + oc];
            }
    #pragma unroll
    for (int s = 0; s < 8; ++s) {
        P0[s] += __shfl_xor_sync(0xffffffffu, P0[s], 1);
        P0[s] += __shfl_xor_sync(0xffffffffu, P0[s], 2);
        P1[s] += __shfl_xor_sync(0xffffffffu, P1[s], 1);
        P1[s] += __shfl_xor_sync(0xffffffffu, P1[s], 2);
        P2[s] += __shfl_xor_sync(0xffffffffu, P2[s], 2);
        P2[s] += __shfl_xor_sync(0xffffffffu, P2[s], 1);
    }
    if (t == 0) {
        #pragma unroll
        for (int s = 0; s < 8; ++s) {
            const int row = wm*64 + (s >> 1)*16 + g + (s & 1)*8;
            red[0*512 + row*4 + wn] = P0[s];
            red[1*512 + row*4 + wn] = P1[s];
            red[2*512 + row*4 + wn] = P2[s];
        }
    }
    __syncthreads();

    if (tid < 128) {
        const int px = tid;
        float sl = 0.f, s0 = 0.f, s1 = 0.f;
        #pragma unroll
        for (int w = 0; w < 4; ++w) {
            sl += red[0*512 + px*4 + w];
            s0 += red[1*512 + px*4 + w];
            s1 += red[2*512 + px*4 + w];
        }
        const int y = y0 + (px >> 4), xg = x0 + (px & 15);
        const int pix = y*Wn + xg;
        out[OUT_LOC + b*HW + pix] = sl + loc_b[0];
        const float a0 = s0 + shape_b[0];
        const float a1 = s1 + shape_b[1];
        out[OUT_SHAPE + (b*2 + 0)*HW + pix] = a0;
        out[OUT_SHAPE + (b*2 + 1)*HW + pix] = a1;
        shv[px*2 + 0] = a0;
        shv[px*2 + 1] = a1;
    }
    __syncthreads();

    // offsets: 128 px x 72 ch
    for (int idx = tid; idx < 128*72; idx += 256) {
        const int p = idx / 72, j = idx % 72;
        const int y = y0 + (p >> 4), xg = x0 + (p & 15);
        float v = shv[p*2]*offset_w[j*2] + shv[p*2+1]*offset_w[j*2+1];
        g_off[((size_t)((b*Hn + y)*Wn + xg))*72 + j] = v;
    }

    // g_t: direct scattered half2 stores from accumulators
    #pragma unroll
    for (int ma = 0; ma < 4; ++ma) {
        const int row0 = wm*64 + ma*16 + g;
        const int pix0 = (b*Hn + y0 + (row0 >> 4))*Wn + x0 + (row0 & 15);
        const int row1 = row0 + 8;
        const int pix1 = (b*Hn + y0 + (row1 >> 4))*Wn + x0 + (row1 & 15);
        #pragma unroll
        for (int na = 0; na < 8; ++na) {
            const int col = wn*64 + na*8 + 2*t;
            *(__half2*)&g_t[(size_t)pix0*Cn + col] =
                __floats2half2_rn(d[ma][na][0], d[ma][na][1]);
            *(__half2*)&g_t[(size_t)pix1*Cn + col] =
                __floats2half2_rn(d[ma][na][2], d[ma][na][3]);
        }
    }
}

// ---------------------------------------------------------------------------
// Kernel 4: deformable conv, fp16 MMA, interleaved gather pipeline
// ---------------------------------------------------------------------------
__global__ void __launch_bounds__(256, 1)
k_deform_mma(const float* __restrict__ cls_w, const float* __restrict__ cls_b,
             const float* __restrict__ bbox_w, const float* __restrict__ bbox_b,
             float* __restrict__ out) {
    extern __shared__ __align__(128) char smem[];
    __half* Asm0 = (__half*)(smem + SM_A0);
    __half* Asm1 = (__half*)(smem + SM_A1);
    __half* Bsm0 = (__half*)(smem + SM_B0);
    __half* Bsm1 = (__half*)(smem + SM_B1);
    float*  red  = (float*)(smem + SM_RED);

    const int tid = threadIdx.x, wid = tid >> 5, lane = tid & 31;
    const int g = lane >> 2, t = lane & 3;
    const int wm = wid & 1, wn = wid >> 1;

    const int tt = blockIdx.x;
    const int b  = blockIdx.y;
    const int y0 = (tt / 6) * 8, x0 = (tt % 6) * 16;

    const int pB = tid >> 2, qS = tid & 3;
    int   yP[2], xP[2], pixb[2];
    #pragma unroll
    for (int ph = 0; ph < 2; ++ph) {
        const int pS = ph*64 + pB;
        yP[ph] = y0 + (pS >> 4);
        xP[ph] = x0 + (pS & 15);
        pixb[ph] = (b*Hn + yP[ph])*Wn + xP[ph];
    }

    float d[4][8][4];
    #pragma unroll
    for (int i = 0; i < 4; ++i)
        #pragma unroll
        for (int j = 0; j < 8; ++j)
            #pragma unroll
            for (int k = 0; k < 4; ++k) d[i][j][k] = 0.f;

    const uint32_t dbOff = (uint32_t)(tid*LDBh)*2;
    const uint32_t db0 = smem_u32(Bsm0) + dbOff, db1 = smem_u32(Bsm1) + dbOff;

    int    ga[2][4];
    float  gw[2][4];
    uint4  u[4];            // transient: 8 fp16 channels per corner
    float2 offA, offB;      // prefetched offsets for next gt

    auto calc_meta = [&](int gt, float2 o0, float2 o1) {
        const int gg = gt / 9, tap = gt - gg*9;
        const int dy = tap/3 - 1, dx = tap%3 - 1;
        #pragma unroll
        for (int ph = 0; ph < 2; ++ph) {
            const float2 off = ph ? o1 : o0;
            const float pyf = (float)(yP[ph] + dy) + off.x;
            const float pxf = (float)(xP[ph] + dx) + off.y;
            const float y0f = floorf(pyf), x0f = floorf(pxf);
            const float wy = pyf - y0f, wx = pxf - x0f;
            const int yi = (int)y0f, xi = (int)x0f;
            #pragma unroll
            for (int cy = 0; cy < 2; ++cy)
                #pragma unroll
                for (int cx = 0; cx < 2; ++cx) {
                    const int k = cy*2 + cx;
                    const int yc = yi + cy, xc = xi + cx;
                    const bool valid = (yc >= 0 && yc < Hn && xc >= 0 && xc < Wn);
                    const int ycc = min(max(yc, 0), Hn - 1);
                    const int xcc = min(max(xc, 0), Wn - 1);
                    const float wv = (cy ? wy : 1.f - wy) * (cx ? wx : 1.f - wx);
                    gw[ph][k] = valid ? wv : 0.f;
                    ga[ph][k] = ((b*Hn + ycc)*Wn + xcc)*Cn + gg*CGn;
                }
        }
    };

// gather one phase (8 fp16 ch per corner)
#define GATHER_SUB(cc, ph) {                                                   \
    const int _chb = ((cc) & 1)*32 + qS*8;                                     \
    u[0] = *(const uint4*)&g_t[(size_t)ga[ph][0] + _chb];                      \
    u[1] = *(const uint4*)&g_t[(size_t)ga[ph][1] + _chb];                      \
    u[2] = *(const uint4*)&g_t[(size_t)ga[ph][2] + _chb];                      \
    u[3] = *(const uint4*)&g_t[(size_t)ga[ph][3] + _chb];                      \
}
#define COMBINE_STS(ph, Abuf) {                                                \
    float r[8];                                                                \
    _Pragma("unroll")                                                          \
    for (int j = 0; j < 8; ++j) r[j] = 0.f;                                    \
    _Pragma("unroll")                                                          \
    for (int k = 0; k < 4; ++k) {                                              \
        const __half2* h = (const __half2*)&u[k];                              \
        const float w = gw[ph][k];                                             \
        _Pragma("unroll")                                                      \
        for (int j = 0; j < 4; ++j) {                                          \
            const float2 v = __half22float2(h[j]);                             \
            r[2*j]   += w * v.x;                                               \
            r[2*j+1] += w * v.y;                                               \
        }                                                                      \
    }                                                                          \
    __half2 o[4];                                                              \
    _Pragma("unroll")                                                          \
    for (int j = 0; j < 4; ++j) o[j] = __floats2half2_rn(r[2*j], r[2*j+1]);    \
    *(uint4*)&(Abuf)[((ph)*64 + pB)*LDAh + qS*8] = *(uint4*)o;                 \
}
#define STAGE_B(cc, db) {                                                      \
    const __half* ws = &g_w2h[(size_t)(cc)*8192 + tid*32];                     \
    _Pragma("unroll")                                                          \
    for (int q = 0; q < 4; ++q) CPA16((db) + q*16, ws + q*8);                  \
    CPA_COMMIT();                                                              \
}
// MMA over chunk in bufX while staging chunk cn into bufY (interleaved)
#define DEFORM_STEP(AX, BX, cn, AY, dbY, hasnext) {                            \
    if (hasnext) { STAGE_B(cn, dbY); GATHER_SUB(cn, 0); }                      \
    MMA_KSTEP(AX, BX, 0)                                                       \
    if (hasnext) { COMBINE_STS(0, AY); GATHER_SUB(cn, 1); }                    \
    MMA_KSTEP(AX, BX, 1)                                                       \
    if (hasnext) { COMBINE_STS(1, AY); }                                       \
    CPA_WAIT0();                                                               \
    __syncthreads();                                                           \
}

    // prologue: meta gt0, stage chunk 0 -> buf0, prefetch gt1 offsets
    offA = *(const float2*)&g_off[(size_t)pixb[0]*72];
    offB = *(const float2*)&g_off[(size_t)pixb[1]*72];
    calc_meta(0, offA, offB);
    offA = *(const float2*)&g_off[(size_t)pixb[0]*72 + 2];
    offB = *(const float2*)&g_off[(size_t)pixb[1]*72 + 2];
    STAGE_B(0, db0);
    GATHER_SUB(0, 0); COMBINE_STS(0, Asm0);
    GATHER_SUB(0, 1); COMBINE_STS(1, Asm0);
    CPA_WAIT0();
    __syncthreads();

    #pragma unroll 1
    for (int c = 0; c < NCHUNK; c += 2) {
        DEFORM_STEP(Asm0, Bsm0, c + 1, Asm1, db1, (c + 1 < NCHUNK))
        if (c + 2 < NCHUNK) {
            const int gt = (c + 2) >> 1;
            calc_meta(gt, offA, offB);
            if (gt + 1 < 36) {
                offA = *(const float2*)&g_off[(size_t)pixb[0]*72 + (gt + 1)*2];
                offB = *(const float2*)&g_off[(size_t)pixb[1]*72 + (gt + 1)*2];
            }
        }
        DEFORM_STEP(Asm1, Bsm1, c + 2, Asm0, db0, (c + 2 < NCHUNK))
    }

    // ---- epilogue: relu + cls/bbox head partials -----------------------
    float P[5][8];
    #pragma unroll
    for (int h = 0; h < 5; ++h)
        #pragma unroll
        for (int s = 0; s < 8; ++s) P[h][s] = 0.f;

    #pragma unroll
    for (int ma = 0; ma < 4; ++ma)
        #pragma unroll
        for (int na = 0; na < 8; ++na)
            #pragma unroll
            for (int ci = 0; ci < 4; ++ci) {
                const int oc = wn*64 + na*8 + 2*t + (ci & 1);
                const int slot = ma*2 + (ci >> 1);
                const float v = fmaxf(d[ma][na][ci], 0.f);
                P[0][slot] += v * cls_w[oc];
                P[1][slot] += v * bbox_w[oc];
                P[2][slot] += v * bbox_w[Cn + oc];
                P[3][slot] += v * bbox_w[2*Cn + oc];
                P[4][slot] += v * bbox_w[3*Cn + oc];
            }
    #pragma unroll
    for (int h = 0; h < 5; ++h)
        #pragma unroll
        for (int s = 0; s < 8; ++s) {
            P[h][s] += __shfl_xor_sync(0xffffffffu, P[h][s], 1);
            P[h][s] += __shfl_xor_sync(0xffffffffu, P[h][s], 2);
        }
    if (t == 0) {
        #pragma unroll
        for (int s = 0; s < 8; ++s) {
            const int row = wm*64 + (s >> 1)*16 + g + (s & 1)*8;
            #pragma unroll
            for (int h = 0; h < 5; ++h)
                red[h*512 + row*4 + wn] = P[h][s];
        }
    }
    __syncthreads();

    if (tid < 128) {
        const int px = tid;
        float s[5] = {0.f, 0.f, 0.f, 0.f, 0.f};
        #pragma unroll
        for (int h = 0; h < 5; ++h)
            #pragma unroll
            for (int w = 0; w < 4; ++w)
                s[h] += red[h*512 + px*4 + w];
        const int y = y0 + (px >> 4), xg = x0 + (px & 15);
        const int pix = y*Wn + xg;
        out[OUT_LOGITS + b*HW + pix]        = s[0] + cls_b[0];
        out[OUT_BBOX + (b*4 + 0)*HW + pix]  = s[1] + bbox_b[0];
        out[OUT_BBOX + (b*4 + 1)*HW + pix]  = s[2] + bbox_b[1];
        out[OUT_BBOX + (b*4 + 2)*HW + pix]  = s[3] + bbox_b[2];
        out[OUT_BBOX + (b*4 + 3)*HW + pix]  = s[4] + bbox_b[3];
    }
}

// ---------------------------------------------------------------------------
extern "C" void kernel_launch(void* const* d_in, const int* in_sizes, int n_in,
                              void* d_out, int out_size) {
    const float* feature  = (const float*)d_in[0];
    const float* conv_w   = (const float*)d_in[1];
    const float* conv_b   = (const float*)d_in[2];
    const float* loc_w    = (const float*)d_in[3];
    const float* loc_b    = (const float*)d_in[4];
    const float* shape_w  = (const float*)d_in[5];
    const float* shape_b  = (const float*)d_in[6];
    const float* offset_w = (const float*)d_in[7];
    const float* adapt_w  = (const float*)d_in[8];
    const float* cls_w    = (const float*)d_in[9];
    const float* cls_b    = (const float*)d_in[10];
    const float* bbox_w   = (const float*)d_in[11];
    const float* bbox_b   = (const float*)d_in[12];
    float* out = (float*)d_out;

    cudaFuncSetAttribute(k_conv1_mma,
        cudaFuncAttributeMaxDynamicSharedMemorySize, SM_TOTAL);
    cudaFuncSetAttribute(k_deform_mma,
        cudaFuncAttributeMaxDynamicSharedMemorySize, SM_TOTAL);

    k_transpose_feat<<<dim3(HW/32, Cn/32, Bn), dim3(32, 8)>>>(feature);
    k_prep_w<<<(2*KTOT*Cn + 255)/256, 256>>>(conv_w, adapt_w);
    k_conv1_mma<<<dim3(72, Bn), 256, SM_TOTAL>>>(conv_b, loc_w, loc_b,
                                                 shape_w, shape_b,
                                                 offset_w, out);
    k_deform_mma<<<dim3(72, Bn), 256, SM_TOTAL>>>(cls_w, cls_b,
                                                  bbox_w, bbox_b, out);
}